// round 9
// baseline (speedup 1.0000x reference)
#include <cuda_runtime.h>
#include <cuda_fp16.h>
#include <math.h>

// ---------------------------------------------------------------------------
// Problem constants
// ---------------------------------------------------------------------------
#define NN 100000
#define DD 128
#define PADK 72        // padded smem row stride (halves), conflict-free ldmatrix
#define MAX_ATTN 850000
#define MAX_MEAN 2100000
#define SCAN_BS 512

// ---------------------------------------------------------------------------
// Scratch (device globals — no allocation allowed)
// ---------------------------------------------------------------------------
__device__ __align__(16) __half g_uvh[(size_t)NN * 256];   // [u(+bias) | v] per node
__device__ __align__(16) __half g_nodeh[(size_t)NN * DD];  // fp16 node_emb
__device__ __align__(16) __half g_aggh[(size_t)NN * DD];   // normalized attn agg
__device__ __align__(16) __half g_meanh[(size_t)NN * DD];  // normalized mean agg
__device__ int   g_csr_cnt[2 * NN];
__device__ int   g_start[2 * NN];   // segment starts (stable)
__device__ int   g_pos[2 * NN];     // fill cursors (mutated by fill)
__device__ int   g_blocksums[SCAN_BS];
__device__ int   g_blockoff[SCAN_BS];
__device__ int   g_aidx[MAX_ATTN];                         // attn CSR entries (dst)
__device__ __align__(8) int2 g_ment[MAX_MEAN];             // mean CSR entries (idx, w-bits)

// ---------------------------------------------------------------------------
// Static stream/event resources
// ---------------------------------------------------------------------------
namespace {
struct StreamRes {
    cudaStream_t s2;
    cudaEvent_t evFork, evJoin;
    StreamRes() {
        cudaStreamCreateWithFlags(&s2, cudaStreamNonBlocking);
        cudaEventCreateWithFlags(&evFork, cudaEventDisableTiming);
        cudaEventCreateWithFlags(&evJoin, cudaEventDisableTiming);
    }
};
StreamRes g_res;
}

// ---------------------------------------------------------------------------
// Helpers
// ---------------------------------------------------------------------------
__device__ __forceinline__ __half2 tanh2(__half2 x) {
    __half2 r;
    asm("tanh.approx.f16x2 %0, %1;"
        : "=r"(*reinterpret_cast<unsigned*>(&r))
        : "r"(*reinterpret_cast<const unsigned*>(&x)));
    return r;
}

__device__ __forceinline__ void h8_to_f8(uint4 p, float* f) {
    float2 t;
    t = __half22float2(*reinterpret_cast<__half2*>(&p.x)); f[0] = t.x; f[1] = t.y;
    t = __half22float2(*reinterpret_cast<__half2*>(&p.y)); f[2] = t.x; f[3] = t.y;
    t = __half22float2(*reinterpret_cast<__half2*>(&p.z)); f[4] = t.x; f[5] = t.y;
    t = __half22float2(*reinterpret_cast<__half2*>(&p.w)); f[6] = t.x; f[7] = t.y;
}

__device__ __forceinline__ unsigned smem_u32(const void* p) {
    return (unsigned)__cvta_generic_to_shared(p);
}

#define LDMX4(r0, r1, r2, r3, addr)                                              \
    asm volatile("ldmatrix.sync.aligned.m8n8.x4.shared.b16 {%0,%1,%2,%3}, [%4];" \
                 : "=r"(r0), "=r"(r1), "=r"(r2), "=r"(r3) : "r"(addr))

#define MMA16816(c, a, b)                                                        \
    asm volatile("mma.sync.aligned.m16n8k16.row.col.f32.f16.f16.f32 "            \
                 "{%0,%1,%2,%3}, {%4,%5,%6,%7}, {%8,%9}, {%0,%1,%2,%3};"         \
                 : "+f"((c)[0]), "+f"((c)[1]), "+f"((c)[2]), "+f"((c)[3])        \
                 : "r"((a)[0]), "r"((a)[1]), "r"((a)[2]), "r"((a)[3]),           \
                   "r"((b)[0]), "r"((b)[1]))

// ---------------------------------------------------------------------------
// 0. Zero CSR counters
// ---------------------------------------------------------------------------
__global__ void zero_cnt(int n2) {
    int i = blockIdx.x * blockDim.x + threadIdx.x;
    if (i < n2) g_csr_cnt[i] = 0;
}

// ---------------------------------------------------------------------------
// CSR build: count -> scan -> fill.
// ---------------------------------------------------------------------------
__global__ void count_edges(const int* __restrict__ er_s, const int* __restrict__ er_d,
                            const int* __restrict__ ee_s, const int* __restrict__ rr_s,
                            int Eer, int Eee, int Err) {
    int i = blockIdx.x * blockDim.x + threadIdx.x;
    if (i < Eer) {
        atomicAdd(&g_csr_cnt[er_s[i]], 1);
        atomicAdd(&g_csr_cnt[NN + er_d[i]], 1);
    } else if (i < Eer + Eee) {
        atomicAdd(&g_csr_cnt[NN + ee_s[i - Eer]], 1);
    } else if (i < Eer + Eee + Err) {
        atomicAdd(&g_csr_cnt[NN + rr_s[i - Eer - Eee]], 1);
    }
}

__global__ void scan_a(int n) {
    __shared__ int sh[SCAN_BS];
    int tid = threadIdx.x;
    int i = blockIdx.x * SCAN_BS + tid;
    int v = (i < n) ? g_csr_cnt[i] : 0;
    sh[tid] = v;
    __syncthreads();
    for (int off = 1; off < SCAN_BS; off <<= 1) {
        int t = (tid >= off) ? sh[tid - off] : 0;
        __syncthreads();
        sh[tid] += t;
        __syncthreads();
    }
    if (i < n) g_start[i] = sh[tid] - v;
    if (tid == SCAN_BS - 1) g_blocksums[blockIdx.x] = sh[tid];
}

__global__ void scan_b(int nb) {
    __shared__ int sh[SCAN_BS];
    int tid = threadIdx.x;
    int v = (tid < nb) ? g_blocksums[tid] : 0;
    sh[tid] = v;
    __syncthreads();
    for (int off = 1; off < SCAN_BS; off <<= 1) {
        int t = (tid >= off) ? sh[tid - off] : 0;
        __syncthreads();
        sh[tid] += t;
        __syncthreads();
    }
    if (tid < nb) g_blockoff[tid] = sh[tid] - v;
}

__global__ void scan_c(int n) {
    int i = blockIdx.x * SCAN_BS + threadIdx.x;
    if (i < n) {
        int v = g_start[i] + g_blockoff[blockIdx.x];
        g_start[i] = v;
        g_pos[i] = v;
    }
}

__global__ void fill_edges(const int* __restrict__ er_s, const int* __restrict__ er_d,
                           const int* __restrict__ ee_s, const int* __restrict__ ee_d,
                           const float* __restrict__ ee_w, const int* __restrict__ rr_s,
                           const int* __restrict__ rr_d,
                           int Eer, int Eee, int Err) {
    int i = blockIdx.x * blockDim.x + threadIdx.x;
    const float one = 1.0f;
    if (i < Eer) {
        int s = er_s[i], d = er_d[i];
        int p = atomicAdd(&g_pos[s], 1);
        g_aidx[p] = d;
        int p2 = atomicAdd(&g_pos[NN + d], 1) - Eer;
        g_ment[p2] = make_int2(s, __float_as_int(one));
    } else if (i < Eer + Eee) {
        int j = i - Eer;
        int p = atomicAdd(&g_pos[NN + ee_s[j]], 1) - Eer;
        g_ment[p] = make_int2(ee_d[j], __float_as_int(ee_w[j]));
    } else if (i < Eer + Eee + Err) {
        int j = i - Eer - Eee;
        int p = atomicAdd(&g_pos[NN + rr_s[j]], 1) - Eer;
        g_ment[p] = make_int2(rr_d[j], __float_as_int(one));
    }
}

// ---------------------------------------------------------------------------
// 1. Projections via tensor cores. grid.y in {0,1,2}:
//    by 0: u = x@Wr^T + b_attn -> uvh[:,0:128]  (also writes fp16 node copy)
//    by 1: v = x@Wh^T          -> uvh[:,128:256]
//    by 2: out = tanh(x@W1^T + b1) -> out (fp32)   [phase 0 of final sum]
// ---------------------------------------------------------------------------
__global__ __launch_bounds__(256) void uv_gemm_mma(const float* __restrict__ A,
                                                   const float* __restrict__ Wattn,
                                                   const float* __restrict__ battn,
                                                   const float* __restrict__ W1,
                                                   const float* __restrict__ b1,
                                                   float* __restrict__ out,
                                                   int M) {
    __shared__ __half As[128 * PADK];
    __shared__ __half Bs[128 * PADK];

    const int by = blockIdx.y;
    const int rowBase = blockIdx.x * 128;
    const int tid = threadIdx.x;
    const int wid = tid >> 5, lane = tid & 31;
    const int m0 = (wid >> 1) * 32;
    const int n0 = (wid & 1) * 64;
    const float* Wb = (by == 2) ? W1 : (Wattn + by * 128);
    const int strideW = (by == 2) ? 128 : 256;
    const float* bias = (by == 2) ? b1 : battn;

    float c[2][8][4];
#pragma unroll
    for (int mt = 0; mt < 2; mt++)
#pragma unroll
        for (int nt = 0; nt < 8; nt++)
#pragma unroll
            for (int q = 0; q < 4; q++) c[mt][nt][q] = 0.f;

    for (int kb = 0; kb < 128; kb += 64) {
        __syncthreads();
#pragma unroll
        for (int it = 0; it < 8; it++) {
            int idx = tid + it * 256;
            int row = idx >> 4, c4 = (idx & 15) * 4;
            int grow = rowBase + row;
            int gr = min(grow, M - 1);
            float4 v = *reinterpret_cast<const float4*>(&A[(size_t)gr * DD + kb + c4]);
            __half2 h01 = __floats2half2_rn(v.x, v.y);
            __half2 h23 = __floats2half2_rn(v.z, v.w);
            uint2 p;
            p.x = *reinterpret_cast<unsigned*>(&h01);
            p.y = *reinterpret_cast<unsigned*>(&h23);
            *reinterpret_cast<uint2*>(&As[row * PADK + c4]) = p;
            if (by == 0 && grow < M)
                reinterpret_cast<uint2*>(g_nodeh)[(size_t)grow * 32 + ((kb + c4) >> 2)] = p;

            float4 w = *reinterpret_cast<const float4*>(&Wb[(size_t)row * strideW + kb + c4]);
            __half2 w01 = __floats2half2_rn(w.x, w.y);
            __half2 w23 = __floats2half2_rn(w.z, w.w);
            uint2 q;
            q.x = *reinterpret_cast<unsigned*>(&w01);
            q.y = *reinterpret_cast<unsigned*>(&w23);
            *reinterpret_cast<uint2*>(&Bs[row * PADK + c4]) = q;
        }
        __syncthreads();

#pragma unroll
        for (int ks = 0; ks < 4; ks++) {
            int k = ks * 16;
            unsigned a[2][4], b[8][2];
#pragma unroll
            for (int mt = 0; mt < 2; mt++) {
                int r = m0 + mt * 16 + ((lane >> 3) & 1) * 8 + (lane & 7);
                int cc = k + (lane >> 4) * 8;
                LDMX4(a[mt][0], a[mt][1], a[mt][2], a[mt][3], smem_u32(&As[r * PADK + cc]));
            }
#pragma unroll
            for (int np = 0; np < 4; np++) {
                int mat = lane >> 3;
                int r = n0 + np * 16 + (mat & 2) * 4 + (lane & 7);
                int cc = k + (mat & 1) * 8;
                unsigned r0, r1, r2, r3;
                LDMX4(r0, r1, r2, r3, smem_u32(&Bs[r * PADK + cc]));
                b[np * 2][0] = r0; b[np * 2][1] = r1;
                b[np * 2 + 1][0] = r2; b[np * 2 + 1][1] = r3;
            }
#pragma unroll
            for (int mt = 0; mt < 2; mt++)
#pragma unroll
                for (int nt = 0; nt < 8; nt++) MMA16816(c[mt][nt], a[mt], b[nt]);
        }
    }

#pragma unroll
    for (int mt = 0; mt < 2; mt++) {
        int row0 = rowBase + m0 + mt * 16 + (lane >> 2);
#pragma unroll
        for (int q = 0; q < 2; q++) {
            int r = row0 + q * 8;
            if (r >= M) continue;
#pragma unroll
            for (int nt = 0; nt < 8; nt++) {
                int col = n0 + nt * 8 + (lane & 3) * 2;
                float v0 = c[mt][nt][q * 2 + 0];
                float v1 = c[mt][nt][q * 2 + 1];
                if (by == 2) {
                    float2 o = make_float2(tanhf(v0 + bias[col]), tanhf(v1 + bias[col + 1]));
                    *reinterpret_cast<float2*>(&out[(size_t)r * DD + col]) = o;
                } else {
                    if (by == 0) { v0 += bias[col]; v1 += bias[col + 1]; }
                    *reinterpret_cast<__half2*>(&g_uvh[(size_t)r * 256 + by * 128 + col]) =
                        __floats2half2_rn(v0, v1);
                }
            }
        }
    }
}

// ---------------------------------------------------------------------------
// 2. Merged gather pass, INTERLEAVED: warp k -> node (k>>1); even k = attn,
//    odd k = mean. Every block holds both warp types so the tanh/shfl-heavy
//    attn chains co-schedule with mean's pure load streams on each SMSP.
// ---------------------------------------------------------------------------
__global__ __launch_bounds__(256) void gather_all(const float* __restrict__ w0,
                                                  const float* __restrict__ w0b,
                                                  int N, int Eer, int totMean) {
    int kg = blockIdx.x * 8 + (threadIdx.x >> 5);
    int lane = threadIdx.x & 31;
    int lh = lane & 15;       // lane within half
    int half = lane >> 4;     // 0 or 1
    int node = kg >> 1;
    int isMean = kg & 1;
    if (node >= N) return;

    const uint4* uv4 = reinterpret_cast<const uint4*>(g_uvh);   // 32 uint4/node
    const uint4* nh4 = reinterpret_cast<const uint4*>(g_nodeh); // 16 uint4/node

    if (!isMean) {
        // ---- attention segment for node s ----
        int s = node;
        int beg = g_start[s];
        int end = (s == N - 1) ? Eer : g_start[s + 1];

        uint4 vp = __ldg(&uv4[(size_t)s * 32 + 16 + lh]);
        __half2 vh0 = *reinterpret_cast<__half2*>(&vp.x);
        __half2 vh1 = *reinterpret_cast<__half2*>(&vp.y);
        __half2 vh2 = *reinterpret_cast<__half2*>(&vp.z);
        __half2 vh3 = *reinterpret_cast<__half2*>(&vp.w);
        float w[8];
        float4 wa = __ldg(&reinterpret_cast<const float4*>(w0)[2 * lh]);
        float4 wb = __ldg(&reinterpret_cast<const float4*>(w0)[2 * lh + 1]);
        w[0] = wa.x; w[1] = wa.y; w[2] = wa.z; w[3] = wa.w;
        w[4] = wb.x; w[5] = wb.y; w[6] = wb.z; w[7] = wb.w;
        float b0 = __ldg(w0b);

        float acc[8] = {0, 0, 0, 0, 0, 0, 0, 0};
        float ssum = 0.f;

        for (int p = beg; p < end; p += 32) {
            int m = end - p;
            if (m > 32) m = 32;
            int myd = (lane < m) ? __ldg(&g_aidx[p + lane]) : 0;
            for (int j = 0; j < m; j += 4) {
                int eA = j + half, eB = j + 2 + half;
                bool vA = (eA < m), vB = (eB < m);
                int dA = __shfl_sync(0xffffffffu, myd, vA ? eA : j);
                int dB = __shfl_sync(0xffffffffu, myd, vB ? eB : j);
                uint4 uA = __ldg(&uv4[(size_t)dA * 32 + lh]);
                uint4 nA = __ldg(&nh4[(size_t)dA * 16 + lh]);
                uint4 uB, nB;
                if (j + 2 < m) {
                    uB = __ldg(&uv4[(size_t)dB * 32 + lh]);
                    nB = __ldg(&nh4[(size_t)dB * 16 + lh]);
                }
                __half2 tA0 = tanh2(__hadd2(*reinterpret_cast<__half2*>(&uA.x), vh0));
                __half2 tA1 = tanh2(__hadd2(*reinterpret_cast<__half2*>(&uA.y), vh1));
                __half2 tA2 = tanh2(__hadd2(*reinterpret_cast<__half2*>(&uA.z), vh2));
                __half2 tA3 = tanh2(__hadd2(*reinterpret_cast<__half2*>(&uA.w), vh3));
                float2 a0 = __half22float2(tA0), a1 = __half22float2(tA1);
                float2 a2 = __half22float2(tA2), a3 = __half22float2(tA3);
                float tA = a0.x * w[0] + a0.y * w[1] + a1.x * w[2] + a1.y * w[3]
                         + a2.x * w[4] + a2.y * w[5] + a3.x * w[6] + a3.y * w[7];

                float tB = 0.f;
                if (j + 2 < m) {
                    __half2 tB0 = tanh2(__hadd2(*reinterpret_cast<__half2*>(&uB.x), vh0));
                    __half2 tB1 = tanh2(__hadd2(*reinterpret_cast<__half2*>(&uB.y), vh1));
                    __half2 tB2 = tanh2(__hadd2(*reinterpret_cast<__half2*>(&uB.z), vh2));
                    __half2 tB3 = tanh2(__hadd2(*reinterpret_cast<__half2*>(&uB.w), vh3));
                    float2 b0f = __half22float2(tB0), b1f = __half22float2(tB1);
                    float2 b2f = __half22float2(tB2), b3f = __half22float2(tB3);
                    tB = b0f.x * w[0] + b0f.y * w[1] + b1f.x * w[2] + b1f.y * w[3]
                       + b2f.x * w[4] + b2f.y * w[5] + b3f.x * w[6] + b3f.y * w[7];
                }
                tA += __shfl_xor_sync(0xffffffffu, tA, 1);
                tB += __shfl_xor_sync(0xffffffffu, tB, 1);
                tA += __shfl_xor_sync(0xffffffffu, tA, 2);
                tB += __shfl_xor_sync(0xffffffffu, tB, 2);
                tA += __shfl_xor_sync(0xffffffffu, tA, 4);
                tB += __shfl_xor_sync(0xffffffffu, tB, 4);
                tA += __shfl_xor_sync(0xffffffffu, tA, 8);
                tB += __shfl_xor_sync(0xffffffffu, tB, 8);

                float evA = vA ? __expf(tA + b0) : 0.f;
                float nf[8];
                h8_to_f8(nA, nf);
#pragma unroll
                for (int q = 0; q < 8; q++) acc[q] += evA * nf[q];
                ssum += evA;

                if (j + 2 < m) {
                    float evB = vB ? __expf(tB + b0) : 0.f;
                    h8_to_f8(nB, nf);
#pragma unroll
                    for (int q = 0; q < 8; q++) acc[q] += evB * nf[q];
                    ssum += evB;
                }
            }
        }
#pragma unroll
        for (int q = 0; q < 8; q++) acc[q] += __shfl_xor_sync(0xffffffffu, acc[q], 16);
        ssum += __shfl_xor_sync(0xffffffffu, ssum, 16);

        if (half == 0) {
            float inv = 1.f / (ssum + 1e-9f);
            uint4 o;
            __half2 h;
            h = __floats2half2_rn(acc[0] * inv, acc[1] * inv); o.x = *reinterpret_cast<unsigned*>(&h);
            h = __floats2half2_rn(acc[2] * inv, acc[3] * inv); o.y = *reinterpret_cast<unsigned*>(&h);
            h = __floats2half2_rn(acc[4] * inv, acc[5] * inv); o.z = *reinterpret_cast<unsigned*>(&h);
            h = __floats2half2_rn(acc[6] * inv, acc[7] * inv); o.w = *reinterpret_cast<unsigned*>(&h);
            reinterpret_cast<uint4*>(g_aggh)[(size_t)s * 16 + lh] = o;
        }
    } else {
        // ---- mean segment for node kk ----
        int kk = node;
        int beg = g_start[NN + kk] - Eer;
        int end = ((kk == N - 1) ? totMean : (g_start[NN + kk + 1] - Eer));

        float acc[8] = {0, 0, 0, 0, 0, 0, 0, 0};
        float csum = 0.f;

        for (int p = beg; p < end; p += 32) {
            int m = end - p;
            if (m > 32) m = 32;
            int2 ent = (lane < m) ? __ldg(&g_ment[p + lane]) : make_int2(0, 0);
            for (int j = 0; j < m; j += 4) {
                int eA = j + half, eB = j + 2 + half;
                bool vA = (eA < m), vB = (eB < m);
                int selA = vA ? eA : j, selB = vB ? eB : j;
                int dA = __shfl_sync(0xffffffffu, ent.x, selA);
                float wtA = __int_as_float(__shfl_sync(0xffffffffu, ent.y, selA));
                int dB = __shfl_sync(0xffffffffu, ent.x, selB);
                float wtB = __int_as_float(__shfl_sync(0xffffffffu, ent.y, selB));
                if (!vA) wtA = 0.f;
                if (!vB || j + 2 >= m) wtB = 0.f;
                uint4 nA = __ldg(&nh4[(size_t)dA * 16 + lh]);
                uint4 nB;
                if (j + 2 < m) nB = __ldg(&nh4[(size_t)dB * 16 + lh]);
                float nf[8];
                h8_to_f8(nA, nf);
#pragma unroll
                for (int q = 0; q < 8; q++) acc[q] += wtA * nf[q];
                csum += wtA;
                if (j + 2 < m) {
                    h8_to_f8(nB, nf);
#pragma unroll
                    for (int q = 0; q < 8; q++) acc[q] += wtB * nf[q];
                    csum += wtB;
                }
            }
        }
#pragma unroll
        for (int q = 0; q < 8; q++) acc[q] += __shfl_xor_sync(0xffffffffu, acc[q], 16);
        csum += __shfl_xor_sync(0xffffffffu, csum, 16);

        if (half == 0) {
            float inv = 1.f / fmaxf(csum, 1.0f);
            uint4 o;
            __half2 h;
            h = __floats2half2_rn(acc[0] * inv, acc[1] * inv); o.x = *reinterpret_cast<unsigned*>(&h);
            h = __floats2half2_rn(acc[2] * inv, acc[3] * inv); o.y = *reinterpret_cast<unsigned*>(&h);
            h = __floats2half2_rn(acc[4] * inv, acc[5] * inv); o.z = *reinterpret_cast<unsigned*>(&h);
            h = __floats2half2_rn(acc[6] * inv, acc[7] * inv); o.w = *reinterpret_cast<unsigned*>(&h);
            reinterpret_cast<uint4*>(g_meanh)[(size_t)kk * 16 + lh] = o;
        }
    }
}

// ---------------------------------------------------------------------------
// 4. Final GEMM: 2 phases (attn@W2, mean@W3); res seeded from out (phase 0
//    already written by uv_gemm by==2).
// ---------------------------------------------------------------------------
__global__ __launch_bounds__(256) void final_gemm_mma(const float* __restrict__ W2, const float* __restrict__ b2,
                                                      const float* __restrict__ W3, const float* __restrict__ b3,
                                                      float* __restrict__ out, int M) {
    __shared__ __half As[64 * PADK];
    __shared__ __half Bs[128 * PADK];

    const int rowBase = blockIdx.x * 64;
    const int tid = threadIdx.x;
    const int wid = tid >> 5, lane = tid & 31;
    const int m0 = (wid >> 2) * 32;
    const int n0 = (wid & 3) * 32;

    float res[2][4][4];
    // seed from phase-0 output
#pragma unroll
    for (int mt = 0; mt < 2; mt++) {
        int row0 = rowBase + m0 + mt * 16 + (lane >> 2);
#pragma unroll
        for (int q = 0; q < 2; q++) {
            int r = row0 + q * 8;
            int rc = min(r, M - 1);
#pragma unroll
            for (int nt = 0; nt < 4; nt++) {
                int col = n0 + nt * 8 + (lane & 3) * 2;
                float2 v = *reinterpret_cast<const float2*>(&out[(size_t)rc * DD + col]);
                res[mt][nt][q * 2 + 0] = v.x;
                res[mt][nt][q * 2 + 1] = v.y;
            }
        }
    }

    for (int phase = 1; phase < 3; phase++) {
        const float* W = (phase == 1) ? W2 : W3;
        const float* bb = (phase == 1) ? b2 : b3;
        const __half* Ah = (phase == 1) ? g_aggh : g_meanh;

        float c[2][4][4];
#pragma unroll
        for (int mt = 0; mt < 2; mt++)
#pragma unroll
            for (int nt = 0; nt < 4; nt++)
#pragma unroll
                for (int q = 0; q < 4; q++) c[mt][nt][q] = 0.f;

        for (int kb = 0; kb < 128; kb += 64) {
            __syncthreads();
#pragma unroll
            for (int it = 0; it < 4; it++) {
                int idx = tid + it * 256;
                int row = idx >> 4, c4 = (idx & 15) * 4;
                int gr = min(rowBase + row, M - 1);
                uint2 p = *reinterpret_cast<const uint2*>(&Ah[(size_t)gr * DD + kb + c4]);
                *reinterpret_cast<uint2*>(&As[row * PADK + c4]) = p;
            }
#pragma unroll
            for (int it = 0; it < 8; it++) {
                int idx = tid + it * 256;
                int n = idx >> 4, c4 = (idx & 15) * 4;
                float4 w = *reinterpret_cast<const float4*>(&W[(size_t)n * DD + kb + c4]);
                __half2 w01 = __floats2half2_rn(w.x, w.y);
                __half2 w23 = __floats2half2_rn(w.z, w.w);
                uint2 q;
                q.x = *reinterpret_cast<unsigned*>(&w01);
                q.y = *reinterpret_cast<unsigned*>(&w23);
                *reinterpret_cast<uint2*>(&Bs[n * PADK + c4]) = q;
            }
            __syncthreads();

#pragma unroll
            for (int ks = 0; ks < 4; ks++) {
                int k = ks * 16;
                unsigned a[2][4], b[4][2];
#pragma unroll
                for (int mt = 0; mt < 2; mt++) {
                    int r = m0 + mt * 16 + ((lane >> 3) & 1) * 8 + (lane & 7);
                    int cc = k + (lane >> 4) * 8;
                    LDMX4(a[mt][0], a[mt][1], a[mt][2], a[mt][3], smem_u32(&As[r * PADK + cc]));
                }
#pragma unroll
                for (int np = 0; np < 2; np++) {
                    int mat = lane >> 3;
                    int r = n0 + np * 16 + (mat & 2) * 4 + (lane & 7);
                    int cc = k + (mat & 1) * 8;
                    unsigned r0, r1, r2, r3;
                    LDMX4(r0, r1, r2, r3, smem_u32(&Bs[r * PADK + cc]));
                    b[np * 2][0] = r0; b[np * 2][1] = r1;
                    b[np * 2 + 1][0] = r2; b[np * 2 + 1][1] = r3;
                }
#pragma unroll
                for (int mt = 0; mt < 2; mt++)
#pragma unroll
                    for (int nt = 0; nt < 4; nt++) MMA16816(c[mt][nt], a[mt], b[nt]);
            }
        }

#pragma unroll
        for (int mt = 0; mt < 2; mt++)
#pragma unroll
            for (int nt = 0; nt < 4; nt++) {
                int col = n0 + nt * 8 + (lane & 3) * 2;
                float bj0 = bb[col], bj1 = bb[col + 1];
                res[mt][nt][0] += tanhf(c[mt][nt][0] + bj0);
                res[mt][nt][1] += tanhf(c[mt][nt][1] + bj1);
                res[mt][nt][2] += tanhf(c[mt][nt][2] + bj0);
                res[mt][nt][3] += tanhf(c[mt][nt][3] + bj1);
            }
    }

#pragma unroll
    for (int mt = 0; mt < 2; mt++) {
        int row0 = rowBase + m0 + mt * 16 + (lane >> 2);
#pragma unroll
        for (int q = 0; q < 2; q++) {
            int r = row0 + q * 8;
            if (r >= M) continue;
#pragma unroll
            for (int nt = 0; nt < 4; nt++) {
                int col = n0 + nt * 8 + (lane & 3) * 2;
                float2 v = make_float2(res[mt][nt][q * 2 + 0], res[mt][nt][q * 2 + 1]);
                *reinterpret_cast<float2*>(&out[(size_t)r * DD + col]) = v;
            }
        }
    }
}

// ---------------------------------------------------------------------------
// Launcher — fork/join: CSR build (s2) overlaps uv/phase0 GEMM (main stream)
// ---------------------------------------------------------------------------
extern "C" void kernel_launch(void* const* d_in, const int* in_sizes, int n_in,
                              void* d_out, int out_size) {
    const float* node   = (const float*)d_in[0];
    const int*   er_src = (const int*)d_in[1];
    const int*   er_dst = (const int*)d_in[2];
    const int*   ee_src = (const int*)d_in[3];
    const int*   ee_dst = (const int*)d_in[4];
    const float* ee_w   = (const float*)d_in[5];
    const int*   rr_src = (const int*)d_in[6];
    const int*   rr_dst = (const int*)d_in[7];
    const float* W_attn = (const float*)d_in[8];
    const float* b_attn = (const float*)d_in[9];
    const float* w0_w   = (const float*)d_in[10];
    const float* w0_b   = (const float*)d_in[11];
    const float* W1     = (const float*)d_in[12];
    const float* b1     = (const float*)d_in[13];
    const float* W2     = (const float*)d_in[14];
    const float* b2     = (const float*)d_in[15];
    const float* W3     = (const float*)d_in[16];
    const float* b3     = (const float*)d_in[17];
    float* out = (float*)d_out;

    int N    = in_sizes[0] / DD;
    int E_er = in_sizes[1];
    int E_ee = in_sizes[3];
    int E_rr = in_sizes[6];

    int Etot    = E_er + E_ee + E_rr;
    int totMean = E_er + E_ee + E_rr;      // mean entries (rebased)
    int n2      = 2 * N;
    int nScanBlk = (n2 + SCAN_BS - 1) / SCAN_BS;

    cudaStream_t s2 = g_res.s2;

    cudaEventRecord(g_res.evFork, 0);
    cudaStreamWaitEvent(s2, g_res.evFork, 0);

    // --- s2: CSR build chain ---
    zero_cnt<<<(n2 + 255) / 256, 256, 0, s2>>>(n2);
    count_edges<<<(Etot + 255) / 256, 256, 0, s2>>>(er_src, er_dst, ee_src, rr_src,
                                                    E_er, E_ee, E_rr);
    scan_a<<<nScanBlk, SCAN_BS, 0, s2>>>(n2);
    scan_b<<<1, SCAN_BS, 0, s2>>>(nScanBlk);
    scan_c<<<nScanBlk, SCAN_BS, 0, s2>>>(n2);
    fill_edges<<<(Etot + 255) / 256, 256, 0, s2>>>(er_src, er_dst, ee_src, ee_dst, ee_w,
                                                   rr_src, rr_dst, E_er, E_ee, E_rr);

    // --- main stream: u, v projections + phase-0 output GEMM ---
    {
        dim3 grid((N + 127) / 128, 3);
        uv_gemm_mma<<<grid, 256>>>(node, W_attn, b_attn, W1, b1, out, N);
    }

    cudaEventRecord(g_res.evJoin, s2);
    cudaStreamWaitEvent(0, g_res.evJoin, 0);

    // merged + interleaved gather pass (attn + mean), no atomics
    gather_all<<<(2 * N + 7) / 8, 256>>>(w0_w, w0_b, N, E_er, totMean);
    // final GEMM: phases 1-2, accumulating onto phase-0 output
    final_gemm_mma<<<(N + 63) / 64, 256>>>(W2, b2, W3, b3, out, N);
}

// round 10
// speedup vs baseline: 1.0417x; 1.0417x over previous
#include <cuda_runtime.h>
#include <cuda_fp16.h>
#include <math.h>

// ---------------------------------------------------------------------------
// Problem constants
// ---------------------------------------------------------------------------
#define NN 100000
#define DD 128
#define PADK 72        // padded smem row stride (halves), conflict-free ldmatrix
#define MAX_ATTN 850000
#define MAX_MEAN 2100000
#define SCAN_BS 512

// ---------------------------------------------------------------------------
// Scratch (device globals — no allocation allowed)
// ---------------------------------------------------------------------------
__device__ __align__(16) __half g_uvh[(size_t)NN * 256];   // [u(+bias) | v] per node
__device__ __align__(16) __half g_nodeh[(size_t)NN * DD];  // fp16 node_emb
__device__ __align__(16) __half g_aggh[(size_t)NN * DD];   // normalized attn agg
__device__ __align__(16) __half g_meanh[(size_t)NN * DD];  // normalized mean agg
__device__ int   g_csr_cnt[2 * NN];
__device__ int   g_start[2 * NN];   // segment starts (stable)
__device__ int   g_pos[2 * NN];     // fill cursors (mutated by fill)
__device__ int   g_blocksums[SCAN_BS];
__device__ int   g_blockoff[SCAN_BS];
__device__ int   g_aidx[MAX_ATTN];                         // attn CSR entries (dst)
__device__ __align__(8) int2 g_ment[MAX_MEAN];             // mean CSR entries (idx, w-bits)

// ---------------------------------------------------------------------------
// Static stream/event resources
// ---------------------------------------------------------------------------
namespace {
struct StreamRes {
    cudaStream_t s2;
    cudaEvent_t evFork, evJoin;
    StreamRes() {
        cudaStreamCreateWithFlags(&s2, cudaStreamNonBlocking);
        cudaEventCreateWithFlags(&evFork, cudaEventDisableTiming);
        cudaEventCreateWithFlags(&evJoin, cudaEventDisableTiming);
    }
};
StreamRes g_res;
}

// ---------------------------------------------------------------------------
// Helpers
// ---------------------------------------------------------------------------
__device__ __forceinline__ __half2 tanh2(__half2 x) {
    __half2 r;
    asm("tanh.approx.f16x2 %0, %1;"
        : "=r"(*reinterpret_cast<unsigned*>(&r))
        : "r"(*reinterpret_cast<const unsigned*>(&x)));
    return r;
}

__device__ __forceinline__ void h8_to_f8(uint4 p, float* f) {
    float2 t;
    t = __half22float2(*reinterpret_cast<__half2*>(&p.x)); f[0] = t.x; f[1] = t.y;
    t = __half22float2(*reinterpret_cast<__half2*>(&p.y)); f[2] = t.x; f[3] = t.y;
    t = __half22float2(*reinterpret_cast<__half2*>(&p.z)); f[4] = t.x; f[5] = t.y;
    t = __half22float2(*reinterpret_cast<__half2*>(&p.w)); f[6] = t.x; f[7] = t.y;
}

__device__ __forceinline__ unsigned smem_u32(const void* p) {
    return (unsigned)__cvta_generic_to_shared(p);
}

#define LDMX4(r0, r1, r2, r3, addr)                                              \
    asm volatile("ldmatrix.sync.aligned.m8n8.x4.shared.b16 {%0,%1,%2,%3}, [%4];" \
                 : "=r"(r0), "=r"(r1), "=r"(r2), "=r"(r3) : "r"(addr))

#define MMA16816(c, a, b)                                                        \
    asm volatile("mma.sync.aligned.m16n8k16.row.col.f32.f16.f16.f32 "            \
                 "{%0,%1,%2,%3}, {%4,%5,%6,%7}, {%8,%9}, {%0,%1,%2,%3};"         \
                 : "+f"((c)[0]), "+f"((c)[1]), "+f"((c)[2]), "+f"((c)[3])        \
                 : "r"((a)[0]), "r"((a)[1]), "r"((a)[2]), "r"((a)[3]),           \
                   "r"((b)[0]), "r"((b)[1]))

// ---------------------------------------------------------------------------
// 0. Zero CSR counters
// ---------------------------------------------------------------------------
__global__ void zero_cnt(int n2) {
    int i = blockIdx.x * blockDim.x + threadIdx.x;
    if (i < n2) g_csr_cnt[i] = 0;
}

// ---------------------------------------------------------------------------
// CSR build: count -> scan -> fill.
// ---------------------------------------------------------------------------
__global__ void count_edges(const int* __restrict__ er_s, const int* __restrict__ er_d,
                            const int* __restrict__ ee_s, const int* __restrict__ rr_s,
                            int Eer, int Eee, int Err) {
    int i = blockIdx.x * blockDim.x + threadIdx.x;
    if (i < Eer) {
        atomicAdd(&g_csr_cnt[er_s[i]], 1);
        atomicAdd(&g_csr_cnt[NN + er_d[i]], 1);
    } else if (i < Eer + Eee) {
        atomicAdd(&g_csr_cnt[NN + ee_s[i - Eer]], 1);
    } else if (i < Eer + Eee + Err) {
        atomicAdd(&g_csr_cnt[NN + rr_s[i - Eer - Eee]], 1);
    }
}

__global__ void scan_a(int n) {
    __shared__ int sh[SCAN_BS];
    int tid = threadIdx.x;
    int i = blockIdx.x * SCAN_BS + tid;
    int v = (i < n) ? g_csr_cnt[i] : 0;
    sh[tid] = v;
    __syncthreads();
    for (int off = 1; off < SCAN_BS; off <<= 1) {
        int t = (tid >= off) ? sh[tid - off] : 0;
        __syncthreads();
        sh[tid] += t;
        __syncthreads();
    }
    if (i < n) g_start[i] = sh[tid] - v;
    if (tid == SCAN_BS - 1) g_blocksums[blockIdx.x] = sh[tid];
}

__global__ void scan_b(int nb) {
    __shared__ int sh[SCAN_BS];
    int tid = threadIdx.x;
    int v = (tid < nb) ? g_blocksums[tid] : 0;
    sh[tid] = v;
    __syncthreads();
    for (int off = 1; off < SCAN_BS; off <<= 1) {
        int t = (tid >= off) ? sh[tid - off] : 0;
        __syncthreads();
        sh[tid] += t;
        __syncthreads();
    }
    if (tid < nb) g_blockoff[tid] = sh[tid] - v;
}

__global__ void scan_c(int n) {
    int i = blockIdx.x * SCAN_BS + threadIdx.x;
    if (i < n) {
        int v = g_start[i] + g_blockoff[blockIdx.x];
        g_start[i] = v;
        g_pos[i] = v;
    }
}

__global__ void fill_edges(const int* __restrict__ er_s, const int* __restrict__ er_d,
                           const int* __restrict__ ee_s, const int* __restrict__ ee_d,
                           const float* __restrict__ ee_w, const int* __restrict__ rr_s,
                           const int* __restrict__ rr_d,
                           int Eer, int Eee, int Err) {
    int i = blockIdx.x * blockDim.x + threadIdx.x;
    const float one = 1.0f;
    if (i < Eer) {
        int s = er_s[i], d = er_d[i];
        int p = atomicAdd(&g_pos[s], 1);
        g_aidx[p] = d;
        int p2 = atomicAdd(&g_pos[NN + d], 1) - Eer;
        g_ment[p2] = make_int2(s, __float_as_int(one));
    } else if (i < Eer + Eee) {
        int j = i - Eer;
        int p = atomicAdd(&g_pos[NN + ee_s[j]], 1) - Eer;
        g_ment[p] = make_int2(ee_d[j], __float_as_int(ee_w[j]));
    } else if (i < Eer + Eee + Err) {
        int j = i - Eer - Eee;
        int p = atomicAdd(&g_pos[NN + rr_s[j]], 1) - Eer;
        g_ment[p] = make_int2(rr_d[j], __float_as_int(one));
    }
}

// ---------------------------------------------------------------------------
// 1. Projections via tensor cores. grid.y in {0,1,2}:
//    by 0: u = x@Wr^T + b_attn -> uvh[:,0:128]  (also writes fp16 node copy)
//    by 1: v = x@Wh^T          -> uvh[:,128:256]
//    by 2: out = tanh(x@W1^T + b1) -> out (fp32)   [phase 0 of final sum]
// ---------------------------------------------------------------------------
__global__ __launch_bounds__(256) void uv_gemm_mma(const float* __restrict__ A,
                                                   const float* __restrict__ Wattn,
                                                   const float* __restrict__ battn,
                                                   const float* __restrict__ W1,
                                                   const float* __restrict__ b1,
                                                   float* __restrict__ out,
                                                   int M) {
    __shared__ __half As[128 * PADK];
    __shared__ __half Bs[128 * PADK];

    const int by = blockIdx.y;
    const int rowBase = blockIdx.x * 128;
    const int tid = threadIdx.x;
    const int wid = tid >> 5, lane = tid & 31;
    const int m0 = (wid >> 1) * 32;
    const int n0 = (wid & 1) * 64;
    const float* Wb = (by == 2) ? W1 : (Wattn + by * 128);
    const int strideW = (by == 2) ? 128 : 256;
    const float* bias = (by == 2) ? b1 : battn;

    float c[2][8][4];
#pragma unroll
    for (int mt = 0; mt < 2; mt++)
#pragma unroll
        for (int nt = 0; nt < 8; nt++)
#pragma unroll
            for (int q = 0; q < 4; q++) c[mt][nt][q] = 0.f;

    for (int kb = 0; kb < 128; kb += 64) {
        __syncthreads();
#pragma unroll
        for (int it = 0; it < 8; it++) {
            int idx = tid + it * 256;
            int row = idx >> 4, c4 = (idx & 15) * 4;
            int grow = rowBase + row;
            int gr = min(grow, M - 1);
            float4 v = *reinterpret_cast<const float4*>(&A[(size_t)gr * DD + kb + c4]);
            __half2 h01 = __floats2half2_rn(v.x, v.y);
            __half2 h23 = __floats2half2_rn(v.z, v.w);
            uint2 p;
            p.x = *reinterpret_cast<unsigned*>(&h01);
            p.y = *reinterpret_cast<unsigned*>(&h23);
            *reinterpret_cast<uint2*>(&As[row * PADK + c4]) = p;
            if (by == 0 && grow < M)
                reinterpret_cast<uint2*>(g_nodeh)[(size_t)grow * 32 + ((kb + c4) >> 2)] = p;

            float4 w = *reinterpret_cast<const float4*>(&Wb[(size_t)row * strideW + kb + c4]);
            __half2 w01 = __floats2half2_rn(w.x, w.y);
            __half2 w23 = __floats2half2_rn(w.z, w.w);
            uint2 q;
            q.x = *reinterpret_cast<unsigned*>(&w01);
            q.y = *reinterpret_cast<unsigned*>(&w23);
            *reinterpret_cast<uint2*>(&Bs[row * PADK + c4]) = q;
        }
        __syncthreads();

#pragma unroll
        for (int ks = 0; ks < 4; ks++) {
            int k = ks * 16;
            unsigned a[2][4], b[8][2];
#pragma unroll
            for (int mt = 0; mt < 2; mt++) {
                int r = m0 + mt * 16 + ((lane >> 3) & 1) * 8 + (lane & 7);
                int cc = k + (lane >> 4) * 8;
                LDMX4(a[mt][0], a[mt][1], a[mt][2], a[mt][3], smem_u32(&As[r * PADK + cc]));
            }
#pragma unroll
            for (int np = 0; np < 4; np++) {
                int mat = lane >> 3;
                int r = n0 + np * 16 + (mat & 2) * 4 + (lane & 7);
                int cc = k + (mat & 1) * 8;
                unsigned r0, r1, r2, r3;
                LDMX4(r0, r1, r2, r3, smem_u32(&Bs[r * PADK + cc]));
                b[np * 2][0] = r0; b[np * 2][1] = r1;
                b[np * 2 + 1][0] = r2; b[np * 2 + 1][1] = r3;
            }
#pragma unroll
            for (int mt = 0; mt < 2; mt++)
#pragma unroll
                for (int nt = 0; nt < 8; nt++) MMA16816(c[mt][nt], a[mt], b[nt]);
        }
    }

#pragma unroll
    for (int mt = 0; mt < 2; mt++) {
        int row0 = rowBase + m0 + mt * 16 + (lane >> 2);
#pragma unroll
        for (int q = 0; q < 2; q++) {
            int r = row0 + q * 8;
            if (r >= M) continue;
#pragma unroll
            for (int nt = 0; nt < 8; nt++) {
                int col = n0 + nt * 8 + (lane & 3) * 2;
                float v0 = c[mt][nt][q * 2 + 0];
                float v1 = c[mt][nt][q * 2 + 1];
                if (by == 2) {
                    float2 o = make_float2(tanhf(v0 + bias[col]), tanhf(v1 + bias[col + 1]));
                    *reinterpret_cast<float2*>(&out[(size_t)r * DD + col]) = o;
                } else {
                    if (by == 0) { v0 += bias[col]; v1 += bias[col + 1]; }
                    *reinterpret_cast<__half2*>(&g_uvh[(size_t)r * 256 + by * 128 + col]) =
                        __floats2half2_rn(v0, v1);
                }
            }
        }
    }
}

// ---------------------------------------------------------------------------
// 2. Merged gather pass, PHASE-SEPARATED (R8 mapping — cache-friendly):
//    warp k < N -> attention for node k; else mean for node k-N.
//    Half-warp per edge (uint4/lane), 2 edges in flight per half.
// ---------------------------------------------------------------------------
__global__ __launch_bounds__(256) void gather_all(const float* __restrict__ w0,
                                                  const float* __restrict__ w0b,
                                                  int N, int Eer, int totMean) {
    int k = blockIdx.x * 8 + (threadIdx.x >> 5);
    int lane = threadIdx.x & 31;
    int lh = lane & 15;       // lane within half
    int half = lane >> 4;     // 0 or 1

    const uint4* uv4 = reinterpret_cast<const uint4*>(g_uvh);   // 32 uint4/node
    const uint4* nh4 = reinterpret_cast<const uint4*>(g_nodeh); // 16 uint4/node

    if (k < N) {
        // ---- attention segment for node s = k ----
        int s = k;
        int beg = g_start[s];
        int end = (s == N - 1) ? Eer : g_start[s + 1];

        uint4 vp = __ldg(&uv4[(size_t)s * 32 + 16 + lh]);
        __half2 vh0 = *reinterpret_cast<__half2*>(&vp.x);
        __half2 vh1 = *reinterpret_cast<__half2*>(&vp.y);
        __half2 vh2 = *reinterpret_cast<__half2*>(&vp.z);
        __half2 vh3 = *reinterpret_cast<__half2*>(&vp.w);
        float w[8];
        float4 wa = __ldg(&reinterpret_cast<const float4*>(w0)[2 * lh]);
        float4 wb = __ldg(&reinterpret_cast<const float4*>(w0)[2 * lh + 1]);
        w[0] = wa.x; w[1] = wa.y; w[2] = wa.z; w[3] = wa.w;
        w[4] = wb.x; w[5] = wb.y; w[6] = wb.z; w[7] = wb.w;
        float b0 = __ldg(w0b);

        float acc[8] = {0, 0, 0, 0, 0, 0, 0, 0};
        float ssum = 0.f;

        for (int p = beg; p < end; p += 32) {
            int m = end - p;
            if (m > 32) m = 32;
            int myd = (lane < m) ? __ldg(&g_aidx[p + lane]) : 0;
            for (int j = 0; j < m; j += 4) {
                int eA = j + half, eB = j + 2 + half;
                bool vA = (eA < m), vB = (eB < m);
                int dA = __shfl_sync(0xffffffffu, myd, vA ? eA : j);
                int dB = __shfl_sync(0xffffffffu, myd, vB ? eB : j);
                uint4 uA = __ldg(&uv4[(size_t)dA * 32 + lh]);
                uint4 nA = __ldg(&nh4[(size_t)dA * 16 + lh]);
                uint4 uB, nB;
                if (j + 2 < m) {
                    uB = __ldg(&uv4[(size_t)dB * 32 + lh]);
                    nB = __ldg(&nh4[(size_t)dB * 16 + lh]);
                }
                __half2 tA0 = tanh2(__hadd2(*reinterpret_cast<__half2*>(&uA.x), vh0));
                __half2 tA1 = tanh2(__hadd2(*reinterpret_cast<__half2*>(&uA.y), vh1));
                __half2 tA2 = tanh2(__hadd2(*reinterpret_cast<__half2*>(&uA.z), vh2));
                __half2 tA3 = tanh2(__hadd2(*reinterpret_cast<__half2*>(&uA.w), vh3));
                float2 a0 = __half22float2(tA0), a1 = __half22float2(tA1);
                float2 a2 = __half22float2(tA2), a3 = __half22float2(tA3);
                float tA = a0.x * w[0] + a0.y * w[1] + a1.x * w[2] + a1.y * w[3]
                         + a2.x * w[4] + a2.y * w[5] + a3.x * w[6] + a3.y * w[7];

                float tB = 0.f;
                if (j + 2 < m) {
                    __half2 tB0 = tanh2(__hadd2(*reinterpret_cast<__half2*>(&uB.x), vh0));
                    __half2 tB1 = tanh2(__hadd2(*reinterpret_cast<__half2*>(&uB.y), vh1));
                    __half2 tB2 = tanh2(__hadd2(*reinterpret_cast<__half2*>(&uB.z), vh2));
                    __half2 tB3 = tanh2(__hadd2(*reinterpret_cast<__half2*>(&uB.w), vh3));
                    float2 b0f = __half22float2(tB0), b1f = __half22float2(tB1);
                    float2 b2f = __half22float2(tB2), b3f = __half22float2(tB3);
                    tB = b0f.x * w[0] + b0f.y * w[1] + b1f.x * w[2] + b1f.y * w[3]
                       + b2f.x * w[4] + b2f.y * w[5] + b3f.x * w[6] + b3f.y * w[7];
                }
                tA += __shfl_xor_sync(0xffffffffu, tA, 1);
                tB += __shfl_xor_sync(0xffffffffu, tB, 1);
                tA += __shfl_xor_sync(0xffffffffu, tA, 2);
                tB += __shfl_xor_sync(0xffffffffu, tB, 2);
                tA += __shfl_xor_sync(0xffffffffu, tA, 4);
                tB += __shfl_xor_sync(0xffffffffu, tB, 4);
                tA += __shfl_xor_sync(0xffffffffu, tA, 8);
                tB += __shfl_xor_sync(0xffffffffu, tB, 8);

                float evA = vA ? __expf(tA + b0) : 0.f;
                float nf[8];
                h8_to_f8(nA, nf);
#pragma unroll
                for (int q = 0; q < 8; q++) acc[q] += evA * nf[q];
                ssum += evA;

                if (j + 2 < m) {
                    float evB = vB ? __expf(tB + b0) : 0.f;
                    h8_to_f8(nB, nf);
#pragma unroll
                    for (int q = 0; q < 8; q++) acc[q] += evB * nf[q];
                    ssum += evB;
                }
            }
        }
#pragma unroll
        for (int q = 0; q < 8; q++) acc[q] += __shfl_xor_sync(0xffffffffu, acc[q], 16);
        ssum += __shfl_xor_sync(0xffffffffu, ssum, 16);

        if (half == 0) {
            float inv = 1.f / (ssum + 1e-9f);
            uint4 o;
            __half2 h;
            h = __floats2half2_rn(acc[0] * inv, acc[1] * inv); o.x = *reinterpret_cast<unsigned*>(&h);
            h = __floats2half2_rn(acc[2] * inv, acc[3] * inv); o.y = *reinterpret_cast<unsigned*>(&h);
            h = __floats2half2_rn(acc[4] * inv, acc[5] * inv); o.z = *reinterpret_cast<unsigned*>(&h);
            h = __floats2half2_rn(acc[6] * inv, acc[7] * inv); o.w = *reinterpret_cast<unsigned*>(&h);
            reinterpret_cast<uint4*>(g_aggh)[(size_t)s * 16 + lh] = o;
        }
    } else if (k < 2 * N) {
        // ---- mean segment for node kk = k - N ----
        int kk = k - N;
        int beg = g_start[NN + kk] - Eer;
        int end = ((kk == N - 1) ? totMean : (g_start[NN + kk + 1] - Eer));

        float acc[8] = {0, 0, 0, 0, 0, 0, 0, 0};
        float csum = 0.f;

        for (int p = beg; p < end; p += 32) {
            int m = end - p;
            if (m > 32) m = 32;
            int2 ent = (lane < m) ? __ldg(&g_ment[p + lane]) : make_int2(0, 0);
            for (int j = 0; j < m; j += 4) {
                int eA = j + half, eB = j + 2 + half;
                bool vA = (eA < m), vB = (eB < m);
                int selA = vA ? eA : j, selB = vB ? eB : j;
                int dA = __shfl_sync(0xffffffffu, ent.x, selA);
                float wtA = __int_as_float(__shfl_sync(0xffffffffu, ent.y, selA));
                int dB = __shfl_sync(0xffffffffu, ent.x, selB);
                float wtB = __int_as_float(__shfl_sync(0xffffffffu, ent.y, selB));
                if (!vA) wtA = 0.f;
                if (!vB || j + 2 >= m) wtB = 0.f;
                uint4 nA = __ldg(&nh4[(size_t)dA * 16 + lh]);
                uint4 nB;
                if (j + 2 < m) nB = __ldg(&nh4[(size_t)dB * 16 + lh]);
                float nf[8];
                h8_to_f8(nA, nf);
#pragma unroll
                for (int q = 0; q < 8; q++) acc[q] += wtA * nf[q];
                csum += wtA;
                if (j + 2 < m) {
                    h8_to_f8(nB, nf);
#pragma unroll
                    for (int q = 0; q < 8; q++) acc[q] += wtB * nf[q];
                    csum += wtB;
                }
            }
        }
#pragma unroll
        for (int q = 0; q < 8; q++) acc[q] += __shfl_xor_sync(0xffffffffu, acc[q], 16);
        csum += __shfl_xor_sync(0xffffffffu, csum, 16);

        if (half == 0) {
            float inv = 1.f / fmaxf(csum, 1.0f);
            uint4 o;
            __half2 h;
            h = __floats2half2_rn(acc[0] * inv, acc[1] * inv); o.x = *reinterpret_cast<unsigned*>(&h);
            h = __floats2half2_rn(acc[2] * inv, acc[3] * inv); o.y = *reinterpret_cast<unsigned*>(&h);
            h = __floats2half2_rn(acc[4] * inv, acc[5] * inv); o.z = *reinterpret_cast<unsigned*>(&h);
            h = __floats2half2_rn(acc[6] * inv, acc[7] * inv); o.w = *reinterpret_cast<unsigned*>(&h);
            reinterpret_cast<uint4*>(g_meanh)[(size_t)kk * 16 + lh] = o;
        }
    }
}

// ---------------------------------------------------------------------------
// 4. Final GEMM: 2 phases (attn@W2, mean@W3); res seeded from out (phase 0
//    already written by uv_gemm by==2).
// ---------------------------------------------------------------------------
__global__ __launch_bounds__(256) void final_gemm_mma(const float* __restrict__ W2, const float* __restrict__ b2,
                                                      const float* __restrict__ W3, const float* __restrict__ b3,
                                                      float* __restrict__ out, int M) {
    __shared__ __half As[64 * PADK];
    __shared__ __half Bs[128 * PADK];

    const int rowBase = blockIdx.x * 64;
    const int tid = threadIdx.x;
    const int wid = tid >> 5, lane = tid & 31;
    const int m0 = (wid >> 2) * 32;
    const int n0 = (wid & 3) * 32;

    float res[2][4][4];
    // seed from phase-0 output
#pragma unroll
    for (int mt = 0; mt < 2; mt++) {
        int row0 = rowBase + m0 + mt * 16 + (lane >> 2);
#pragma unroll
        for (int q = 0; q < 2; q++) {
            int r = row0 + q * 8;
            int rc = min(r, M - 1);
#pragma unroll
            for (int nt = 0; nt < 4; nt++) {
                int col = n0 + nt * 8 + (lane & 3) * 2;
                float2 v = *reinterpret_cast<const float2*>(&out[(size_t)rc * DD + col]);
                res[mt][nt][q * 2 + 0] = v.x;
                res[mt][nt][q * 2 + 1] = v.y;
            }
        }
    }

    for (int phase = 1; phase < 3; phase++) {
        const float* W = (phase == 1) ? W2 : W3;
        const float* bb = (phase == 1) ? b2 : b3;
        const __half* Ah = (phase == 1) ? g_aggh : g_meanh;

        float c[2][4][4];
#pragma unroll
        for (int mt = 0; mt < 2; mt++)
#pragma unroll
            for (int nt = 0; nt < 4; nt++)
#pragma unroll
                for (int q = 0; q < 4; q++) c[mt][nt][q] = 0.f;

        for (int kb = 0; kb < 128; kb += 64) {
            __syncthreads();
#pragma unroll
            for (int it = 0; it < 4; it++) {
                int idx = tid + it * 256;
                int row = idx >> 4, c4 = (idx & 15) * 4;
                int gr = min(rowBase + row, M - 1);
                uint2 p = *reinterpret_cast<const uint2*>(&Ah[(size_t)gr * DD + kb + c4]);
                *reinterpret_cast<uint2*>(&As[row * PADK + c4]) = p;
            }
#pragma unroll
            for (int it = 0; it < 8; it++) {
                int idx = tid + it * 256;
                int n = idx >> 4, c4 = (idx & 15) * 4;
                float4 w = *reinterpret_cast<const float4*>(&W[(size_t)n * DD + kb + c4]);
                __half2 w01 = __floats2half2_rn(w.x, w.y);
                __half2 w23 = __floats2half2_rn(w.z, w.w);
                uint2 q;
                q.x = *reinterpret_cast<unsigned*>(&w01);
                q.y = *reinterpret_cast<unsigned*>(&w23);
                *reinterpret_cast<uint2*>(&Bs[n * PADK + c4]) = q;
            }
            __syncthreads();

#pragma unroll
            for (int ks = 0; ks < 4; ks++) {
                int k = ks * 16;
                unsigned a[2][4], b[4][2];
#pragma unroll
                for (int mt = 0; mt < 2; mt++) {
                    int r = m0 + mt * 16 + ((lane >> 3) & 1) * 8 + (lane & 7);
                    int cc = k + (lane >> 4) * 8;
                    LDMX4(a[mt][0], a[mt][1], a[mt][2], a[mt][3], smem_u32(&As[r * PADK + cc]));
                }
#pragma unroll
                for (int np = 0; np < 2; np++) {
                    int mat = lane >> 3;
                    int r = n0 + np * 16 + (mat & 2) * 4 + (lane & 7);
                    int cc = k + (mat & 1) * 8;
                    unsigned r0, r1, r2, r3;
                    LDMX4(r0, r1, r2, r3, smem_u32(&Bs[r * PADK + cc]));
                    b[np * 2][0] = r0; b[np * 2][1] = r1;
                    b[np * 2 + 1][0] = r2; b[np * 2 + 1][1] = r3;
                }
#pragma unroll
                for (int mt = 0; mt < 2; mt++)
#pragma unroll
                    for (int nt = 0; nt < 4; nt++) MMA16816(c[mt][nt], a[mt], b[nt]);
            }
        }

#pragma unroll
        for (int mt = 0; mt < 2; mt++)
#pragma unroll
            for (int nt = 0; nt < 4; nt++) {
                int col = n0 + nt * 8 + (lane & 3) * 2;
                float bj0 = bb[col], bj1 = bb[col + 1];
                res[mt][nt][0] += tanhf(c[mt][nt][0] + bj0);
                res[mt][nt][1] += tanhf(c[mt][nt][1] + bj1);
                res[mt][nt][2] += tanhf(c[mt][nt][2] + bj0);
                res[mt][nt][3] += tanhf(c[mt][nt][3] + bj1);
            }
    }

#pragma unroll
    for (int mt = 0; mt < 2; mt++) {
        int row0 = rowBase + m0 + mt * 16 + (lane >> 2);
#pragma unroll
        for (int q = 0; q < 2; q++) {
            int r = row0 + q * 8;
            if (r >= M) continue;
#pragma unroll
            for (int nt = 0; nt < 4; nt++) {
                int col = n0 + nt * 8 + (lane & 3) * 2;
                float2 v = make_float2(res[mt][nt][q * 2 + 0], res[mt][nt][q * 2 + 1]);
                *reinterpret_cast<float2*>(&out[(size_t)r * DD + col]) = v;
            }
        }
    }
}

// ---------------------------------------------------------------------------
// Launcher — fork/join: CSR build (s2) overlaps uv/phase0 GEMM (main stream)
// ---------------------------------------------------------------------------
extern "C" void kernel_launch(void* const* d_in, const int* in_sizes, int n_in,
                              void* d_out, int out_size) {
    const float* node   = (const float*)d_in[0];
    const int*   er_src = (const int*)d_in[1];
    const int*   er_dst = (const int*)d_in[2];
    const int*   ee_src = (const int*)d_in[3];
    const int*   ee_dst = (const int*)d_in[4];
    const float* ee_w   = (const float*)d_in[5];
    const int*   rr_src = (const int*)d_in[6];
    const int*   rr_dst = (const int*)d_in[7];
    const float* W_attn = (const float*)d_in[8];
    const float* b_attn = (const float*)d_in[9];
    const float* w0_w   = (const float*)d_in[10];
    const float* w0_b   = (const float*)d_in[11];
    const float* W1     = (const float*)d_in[12];
    const float* b1     = (const float*)d_in[13];
    const float* W2     = (const float*)d_in[14];
    const float* b2     = (const float*)d_in[15];
    const float* W3     = (const float*)d_in[16];
    const float* b3     = (const float*)d_in[17];
    float* out = (float*)d_out;

    int N    = in_sizes[0] / DD;
    int E_er = in_sizes[1];
    int E_ee = in_sizes[3];
    int E_rr = in_sizes[6];

    int Etot    = E_er + E_ee + E_rr;
    int totMean = E_er + E_ee + E_rr;      // mean entries (rebased)
    int n2      = 2 * N;
    int nScanBlk = (n2 + SCAN_BS - 1) / SCAN_BS;

    cudaStream_t s2 = g_res.s2;

    cudaEventRecord(g_res.evFork, 0);
    cudaStreamWaitEvent(s2, g_res.evFork, 0);

    // --- s2: CSR build chain ---
    zero_cnt<<<(n2 + 255) / 256, 256, 0, s2>>>(n2);
    count_edges<<<(Etot + 255) / 256, 256, 0, s2>>>(er_src, er_dst, ee_src, rr_src,
                                                    E_er, E_ee, E_rr);
    scan_a<<<nScanBlk, SCAN_BS, 0, s2>>>(n2);
    scan_b<<<1, SCAN_BS, 0, s2>>>(nScanBlk);
    scan_c<<<nScanBlk, SCAN_BS, 0, s2>>>(n2);
    fill_edges<<<(Etot + 255) / 256, 256, 0, s2>>>(er_src, er_dst, ee_src, ee_dst, ee_w,
                                                   rr_src, rr_dst, E_er, E_ee, E_rr);

    // --- main stream: u, v projections + phase-0 output GEMM ---
    {
        dim3 grid((N + 127) / 128, 3);
        uv_gemm_mma<<<grid, 256>>>(node, W_attn, b_attn, W1, b1, out, N);
    }

    cudaEventRecord(g_res.evJoin, s2);
    cudaStreamWaitEvent(0, g_res.evJoin, 0);

    // merged gather pass (attn + mean), phase-separated, no atomics
    gather_all<<<(2 * N + 7) / 8, 256>>>(w0_w, w0_b, N, E_er, totMean);
    // final GEMM: phases 1-2, accumulating onto phase-0 output
    final_gemm_mma<<<(N + 63) / 64, 256>>>(W2, b2, W3, b3, out, N);
}

// round 11
// speedup vs baseline: 1.2295x; 1.1802x over previous
#include <cuda_runtime.h>
#include <cuda_fp16.h>
#include <math.h>

// ---------------------------------------------------------------------------
// Problem constants
// ---------------------------------------------------------------------------
#define NN 100000
#define DD 128
#define PADK 72        // padded smem row stride (halves), conflict-free ldmatrix
#define MAX_ATTN 850000
#define MAX_MEAN 2100000
#define SCAN_BS 512

// ---------------------------------------------------------------------------
// Scratch (device globals — no allocation allowed)
// ---------------------------------------------------------------------------
__device__ __align__(16) __half g_uvh[(size_t)NN * 256];   // [u(+bias) | v] per node
__device__ __align__(16) __half g_nodeh[(size_t)NN * DD];  // fp16 node_emb
__device__ __align__(16) __half g_aggh[(size_t)NN * DD];   // normalized attn agg
__device__ __align__(16) __half g_meanh[(size_t)NN * DD];  // normalized mean agg
__device__ int   g_csr_cnt[2 * NN];
__device__ int   g_start[2 * NN];   // segment starts (stable)
__device__ int   g_pos[2 * NN];     // fill cursors (mutated by fill)
__device__ int   g_blocksums[SCAN_BS];
__device__ int   g_blockoff[SCAN_BS];
__device__ int   g_aidx[MAX_ATTN];                         // attn CSR entries (dst)
__device__ __align__(8) int2 g_ment[MAX_MEAN];             // mean CSR entries (idx, w-bits)

// ---------------------------------------------------------------------------
// Static stream/event resources
// ---------------------------------------------------------------------------
namespace {
struct StreamRes {
    cudaStream_t s2;
    cudaEvent_t evFork, evJoin;
    StreamRes() {
        cudaStreamCreateWithFlags(&s2, cudaStreamNonBlocking);
        cudaEventCreateWithFlags(&evFork, cudaEventDisableTiming);
        cudaEventCreateWithFlags(&evJoin, cudaEventDisableTiming);
    }
};
StreamRes g_res;
}

// ---------------------------------------------------------------------------
// Helpers
// ---------------------------------------------------------------------------
__device__ __forceinline__ __half2 tanh2(__half2 x) {
    __half2 r;
    asm("tanh.approx.f16x2 %0, %1;"
        : "=r"(*reinterpret_cast<unsigned*>(&r))
        : "r"(*reinterpret_cast<const unsigned*>(&x)));
    return r;
}

__device__ __forceinline__ void h8_to_f8(uint4 p, float* f) {
    float2 t;
    t = __half22float2(*reinterpret_cast<__half2*>(&p.x)); f[0] = t.x; f[1] = t.y;
    t = __half22float2(*reinterpret_cast<__half2*>(&p.y)); f[2] = t.x; f[3] = t.y;
    t = __half22float2(*reinterpret_cast<__half2*>(&p.z)); f[4] = t.x; f[5] = t.y;
    t = __half22float2(*reinterpret_cast<__half2*>(&p.w)); f[6] = t.x; f[7] = t.y;
}

__device__ __forceinline__ unsigned smem_u32(const void* p) {
    return (unsigned)__cvta_generic_to_shared(p);
}

#define LDMX4(r0, r1, r2, r3, addr)                                              \
    asm volatile("ldmatrix.sync.aligned.m8n8.x4.shared.b16 {%0,%1,%2,%3}, [%4];" \
                 : "=r"(r0), "=r"(r1), "=r"(r2), "=r"(r3) : "r"(addr))

#define MMA16816(c, a, b)                                                        \
    asm volatile("mma.sync.aligned.m16n8k16.row.col.f32.f16.f16.f32 "            \
                 "{%0,%1,%2,%3}, {%4,%5,%6,%7}, {%8,%9}, {%0,%1,%2,%3};"         \
                 : "+f"((c)[0]), "+f"((c)[1]), "+f"((c)[2]), "+f"((c)[3])        \
                 : "r"((a)[0]), "r"((a)[1]), "r"((a)[2]), "r"((a)[3]),           \
                   "r"((b)[0]), "r"((b)[1]))

// ---------------------------------------------------------------------------
// 0. Zero CSR counters
// ---------------------------------------------------------------------------
__global__ void zero_cnt(int n2) {
    int i = blockIdx.x * blockDim.x + threadIdx.x;
    if (i < n2) g_csr_cnt[i] = 0;
}

// ---------------------------------------------------------------------------
// CSR build: count -> scan -> fill.
// ---------------------------------------------------------------------------
__global__ void count_edges(const int* __restrict__ er_s, const int* __restrict__ er_d,
                            const int* __restrict__ ee_s, const int* __restrict__ rr_s,
                            int Eer, int Eee, int Err) {
    int i = blockIdx.x * blockDim.x + threadIdx.x;
    if (i < Eer) {
        atomicAdd(&g_csr_cnt[er_s[i]], 1);
        atomicAdd(&g_csr_cnt[NN + er_d[i]], 1);
    } else if (i < Eer + Eee) {
        atomicAdd(&g_csr_cnt[NN + ee_s[i - Eer]], 1);
    } else if (i < Eer + Eee + Err) {
        atomicAdd(&g_csr_cnt[NN + rr_s[i - Eer - Eee]], 1);
    }
}

__global__ void scan_a(int n) {
    __shared__ int sh[SCAN_BS];
    int tid = threadIdx.x;
    int i = blockIdx.x * SCAN_BS + tid;
    int v = (i < n) ? g_csr_cnt[i] : 0;
    sh[tid] = v;
    __syncthreads();
    for (int off = 1; off < SCAN_BS; off <<= 1) {
        int t = (tid >= off) ? sh[tid - off] : 0;
        __syncthreads();
        sh[tid] += t;
        __syncthreads();
    }
    if (i < n) g_start[i] = sh[tid] - v;
    if (tid == SCAN_BS - 1) g_blocksums[blockIdx.x] = sh[tid];
}

__global__ void scan_b(int nb) {
    __shared__ int sh[SCAN_BS];
    int tid = threadIdx.x;
    int v = (tid < nb) ? g_blocksums[tid] : 0;
    sh[tid] = v;
    __syncthreads();
    for (int off = 1; off < SCAN_BS; off <<= 1) {
        int t = (tid >= off) ? sh[tid - off] : 0;
        __syncthreads();
        sh[tid] += t;
        __syncthreads();
    }
    if (tid < nb) g_blockoff[tid] = sh[tid] - v;
}

__global__ void scan_c(int n) {
    int i = blockIdx.x * SCAN_BS + threadIdx.x;
    if (i < n) {
        int v = g_start[i] + g_blockoff[blockIdx.x];
        g_start[i] = v;
        g_pos[i] = v;
    }
}

__global__ void fill_edges(const int* __restrict__ er_s, const int* __restrict__ er_d,
                           const int* __restrict__ ee_s, const int* __restrict__ ee_d,
                           const float* __restrict__ ee_w, const int* __restrict__ rr_s,
                           const int* __restrict__ rr_d,
                           int Eer, int Eee, int Err) {
    int i = blockIdx.x * blockDim.x + threadIdx.x;
    const float one = 1.0f;
    if (i < Eer) {
        int s = er_s[i], d = er_d[i];
        int p = atomicAdd(&g_pos[s], 1);
        g_aidx[p] = d;
        int p2 = atomicAdd(&g_pos[NN + d], 1) - Eer;
        g_ment[p2] = make_int2(s, __float_as_int(one));
    } else if (i < Eer + Eee) {
        int j = i - Eer;
        int p = atomicAdd(&g_pos[NN + ee_s[j]], 1) - Eer;
        g_ment[p] = make_int2(ee_d[j], __float_as_int(ee_w[j]));
    } else if (i < Eer + Eee + Err) {
        int j = i - Eer - Eee;
        int p = atomicAdd(&g_pos[NN + rr_s[j]], 1) - Eer;
        g_ment[p] = make_int2(rr_d[j], __float_as_int(one));
    }
}

// ---------------------------------------------------------------------------
// 1. uv projections via tensor cores (128x128 block tile, 8 warps).
//    by 0: u = x@Wr^T + b_attn (also writes fp16 node copy); by 1: v = x@Wh^T.
// ---------------------------------------------------------------------------
__global__ __launch_bounds__(256) void uv_gemm_mma(const float* __restrict__ A,
                                                   const float* __restrict__ W,
                                                   const float* __restrict__ bias,
                                                   int M) {
    __shared__ __half As[128 * PADK];
    __shared__ __half Bs[128 * PADK];

    const int by = blockIdx.y;
    const int rowBase = blockIdx.x * 128;
    const int tid = threadIdx.x;
    const int wid = tid >> 5, lane = tid & 31;
    const int m0 = (wid >> 1) * 32;
    const int n0 = (wid & 1) * 64;
    const float* Wb = W + by * 128;

    float c[2][8][4];
#pragma unroll
    for (int mt = 0; mt < 2; mt++)
#pragma unroll
        for (int nt = 0; nt < 8; nt++)
#pragma unroll
            for (int q = 0; q < 4; q++) c[mt][nt][q] = 0.f;

    for (int kb = 0; kb < 128; kb += 64) {
        __syncthreads();
#pragma unroll
        for (int it = 0; it < 8; it++) {
            int idx = tid + it * 256;
            int row = idx >> 4, c4 = (idx & 15) * 4;
            int grow = rowBase + row;
            int gr = min(grow, M - 1);
            float4 v = *reinterpret_cast<const float4*>(&A[(size_t)gr * DD + kb + c4]);
            __half2 h01 = __floats2half2_rn(v.x, v.y);
            __half2 h23 = __floats2half2_rn(v.z, v.w);
            uint2 p;
            p.x = *reinterpret_cast<unsigned*>(&h01);
            p.y = *reinterpret_cast<unsigned*>(&h23);
            *reinterpret_cast<uint2*>(&As[row * PADK + c4]) = p;
            if (by == 0 && grow < M)
                reinterpret_cast<uint2*>(g_nodeh)[(size_t)grow * 32 + ((kb + c4) >> 2)] = p;

            float4 w = *reinterpret_cast<const float4*>(&Wb[(size_t)row * 256 + kb + c4]);
            __half2 w01 = __floats2half2_rn(w.x, w.y);
            __half2 w23 = __floats2half2_rn(w.z, w.w);
            uint2 q;
            q.x = *reinterpret_cast<unsigned*>(&w01);
            q.y = *reinterpret_cast<unsigned*>(&w23);
            *reinterpret_cast<uint2*>(&Bs[row * PADK + c4]) = q;
        }
        __syncthreads();

#pragma unroll
        for (int ks = 0; ks < 4; ks++) {
            int k = ks * 16;
            unsigned a[2][4], b[8][2];
#pragma unroll
            for (int mt = 0; mt < 2; mt++) {
                int r = m0 + mt * 16 + ((lane >> 3) & 1) * 8 + (lane & 7);
                int cc = k + (lane >> 4) * 8;
                LDMX4(a[mt][0], a[mt][1], a[mt][2], a[mt][3], smem_u32(&As[r * PADK + cc]));
            }
#pragma unroll
            for (int np = 0; np < 4; np++) {
                int mat = lane >> 3;
                int r = n0 + np * 16 + (mat & 2) * 4 + (lane & 7);
                int cc = k + (mat & 1) * 8;
                unsigned r0, r1, r2, r3;
                LDMX4(r0, r1, r2, r3, smem_u32(&Bs[r * PADK + cc]));
                b[np * 2][0] = r0; b[np * 2][1] = r1;
                b[np * 2 + 1][0] = r2; b[np * 2 + 1][1] = r3;
            }
#pragma unroll
            for (int mt = 0; mt < 2; mt++)
#pragma unroll
                for (int nt = 0; nt < 8; nt++) MMA16816(c[mt][nt], a[mt], b[nt]);
        }
    }

#pragma unroll
    for (int mt = 0; mt < 2; mt++) {
        int row0 = rowBase + m0 + mt * 16 + (lane >> 2);
#pragma unroll
        for (int q = 0; q < 2; q++) {
            int r = row0 + q * 8;
            if (r >= M) continue;
#pragma unroll
            for (int nt = 0; nt < 8; nt++) {
                int col = n0 + nt * 8 + (lane & 3) * 2;
                float v0 = c[mt][nt][q * 2 + 0];
                float v1 = c[mt][nt][q * 2 + 1];
                if (by == 0) { v0 += bias[col]; v1 += bias[col + 1]; }
                *reinterpret_cast<__half2*>(&g_uvh[(size_t)r * 256 + by * 128 + col]) =
                    __floats2half2_rn(v0, v1);
            }
        }
    }
}

// ---------------------------------------------------------------------------
// 2. Merged gather pass, PHASE-SEPARATED (cache-friendly champion mapping):
//    warp k < N -> attention for node k; else mean for node k-N.
//    Half-warp per edge (uint4/lane), 2 edges in flight per half.
// ---------------------------------------------------------------------------
__global__ __launch_bounds__(256) void gather_all(const float* __restrict__ w0,
                                                  const float* __restrict__ w0b,
                                                  int N, int Eer, int totMean) {
    int k = blockIdx.x * 8 + (threadIdx.x >> 5);
    int lane = threadIdx.x & 31;
    int lh = lane & 15;       // lane within half
    int half = lane >> 4;     // 0 or 1

    const uint4* uv4 = reinterpret_cast<const uint4*>(g_uvh);   // 32 uint4/node
    const uint4* nh4 = reinterpret_cast<const uint4*>(g_nodeh); // 16 uint4/node

    if (k < N) {
        // ---- attention segment for node s = k ----
        int s = k;
        int beg = g_start[s];
        int end = (s == N - 1) ? Eer : g_start[s + 1];

        uint4 vp = __ldg(&uv4[(size_t)s * 32 + 16 + lh]);
        __half2 vh0 = *reinterpret_cast<__half2*>(&vp.x);
        __half2 vh1 = *reinterpret_cast<__half2*>(&vp.y);
        __half2 vh2 = *reinterpret_cast<__half2*>(&vp.z);
        __half2 vh3 = *reinterpret_cast<__half2*>(&vp.w);
        float w[8];
        float4 wa = __ldg(&reinterpret_cast<const float4*>(w0)[2 * lh]);
        float4 wb = __ldg(&reinterpret_cast<const float4*>(w0)[2 * lh + 1]);
        w[0] = wa.x; w[1] = wa.y; w[2] = wa.z; w[3] = wa.w;
        w[4] = wb.x; w[5] = wb.y; w[6] = wb.z; w[7] = wb.w;
        float b0 = __ldg(w0b);

        float acc[8] = {0, 0, 0, 0, 0, 0, 0, 0};
        float ssum = 0.f;

        for (int p = beg; p < end; p += 32) {
            int m = end - p;
            if (m > 32) m = 32;
            int myd = (lane < m) ? __ldg(&g_aidx[p + lane]) : 0;
            for (int j = 0; j < m; j += 4) {
                int eA = j + half, eB = j + 2 + half;
                bool vA = (eA < m), vB = (eB < m);
                int dA = __shfl_sync(0xffffffffu, myd, vA ? eA : j);
                int dB = __shfl_sync(0xffffffffu, myd, vB ? eB : j);
                uint4 uA = __ldg(&uv4[(size_t)dA * 32 + lh]);
                uint4 nA = __ldg(&nh4[(size_t)dA * 16 + lh]);
                uint4 uB, nB;
                if (j + 2 < m) {
                    uB = __ldg(&uv4[(size_t)dB * 32 + lh]);
                    nB = __ldg(&nh4[(size_t)dB * 16 + lh]);
                }
                __half2 tA0 = tanh2(__hadd2(*reinterpret_cast<__half2*>(&uA.x), vh0));
                __half2 tA1 = tanh2(__hadd2(*reinterpret_cast<__half2*>(&uA.y), vh1));
                __half2 tA2 = tanh2(__hadd2(*reinterpret_cast<__half2*>(&uA.z), vh2));
                __half2 tA3 = tanh2(__hadd2(*reinterpret_cast<__half2*>(&uA.w), vh3));
                float2 a0 = __half22float2(tA0), a1 = __half22float2(tA1);
                float2 a2 = __half22float2(tA2), a3 = __half22float2(tA3);
                float tA = a0.x * w[0] + a0.y * w[1] + a1.x * w[2] + a1.y * w[3]
                         + a2.x * w[4] + a2.y * w[5] + a3.x * w[6] + a3.y * w[7];

                float tB = 0.f;
                if (j + 2 < m) {
                    __half2 tB0 = tanh2(__hadd2(*reinterpret_cast<__half2*>(&uB.x), vh0));
                    __half2 tB1 = tanh2(__hadd2(*reinterpret_cast<__half2*>(&uB.y), vh1));
                    __half2 tB2 = tanh2(__hadd2(*reinterpret_cast<__half2*>(&uB.z), vh2));
                    __half2 tB3 = tanh2(__hadd2(*reinterpret_cast<__half2*>(&uB.w), vh3));
                    float2 b0f = __half22float2(tB0), b1f = __half22float2(tB1);
                    float2 b2f = __half22float2(tB2), b3f = __half22float2(tB3);
                    tB = b0f.x * w[0] + b0f.y * w[1] + b1f.x * w[2] + b1f.y * w[3]
                       + b2f.x * w[4] + b2f.y * w[5] + b3f.x * w[6] + b3f.y * w[7];
                }
                tA += __shfl_xor_sync(0xffffffffu, tA, 1);
                tB += __shfl_xor_sync(0xffffffffu, tB, 1);
                tA += __shfl_xor_sync(0xffffffffu, tA, 2);
                tB += __shfl_xor_sync(0xffffffffu, tB, 2);
                tA += __shfl_xor_sync(0xffffffffu, tA, 4);
                tB += __shfl_xor_sync(0xffffffffu, tB, 4);
                tA += __shfl_xor_sync(0xffffffffu, tA, 8);
                tB += __shfl_xor_sync(0xffffffffu, tB, 8);

                float evA = vA ? __expf(tA + b0) : 0.f;
                float nf[8];
                h8_to_f8(nA, nf);
#pragma unroll
                for (int q = 0; q < 8; q++) acc[q] += evA * nf[q];
                ssum += evA;

                if (j + 2 < m) {
                    float evB = vB ? __expf(tB + b0) : 0.f;
                    h8_to_f8(nB, nf);
#pragma unroll
                    for (int q = 0; q < 8; q++) acc[q] += evB * nf[q];
                    ssum += evB;
                }
            }
        }
#pragma unroll
        for (int q = 0; q < 8; q++) acc[q] += __shfl_xor_sync(0xffffffffu, acc[q], 16);
        ssum += __shfl_xor_sync(0xffffffffu, ssum, 16);

        if (half == 0) {
            float inv = 1.f / (ssum + 1e-9f);
            uint4 o;
            __half2 h;
            h = __floats2half2_rn(acc[0] * inv, acc[1] * inv); o.x = *reinterpret_cast<unsigned*>(&h);
            h = __floats2half2_rn(acc[2] * inv, acc[3] * inv); o.y = *reinterpret_cast<unsigned*>(&h);
            h = __floats2half2_rn(acc[4] * inv, acc[5] * inv); o.z = *reinterpret_cast<unsigned*>(&h);
            h = __floats2half2_rn(acc[6] * inv, acc[7] * inv); o.w = *reinterpret_cast<unsigned*>(&h);
            reinterpret_cast<uint4*>(g_aggh)[(size_t)s * 16 + lh] = o;
        }
    } else if (k < 2 * N) {
        // ---- mean segment for node kk = k - N ----
        int kk = k - N;
        int beg = g_start[NN + kk] - Eer;
        int end = ((kk == N - 1) ? totMean : (g_start[NN + kk + 1] - Eer));

        float acc[8] = {0, 0, 0, 0, 0, 0, 0, 0};
        float csum = 0.f;

        for (int p = beg; p < end; p += 32) {
            int m = end - p;
            if (m > 32) m = 32;
            int2 ent = (lane < m) ? __ldg(&g_ment[p + lane]) : make_int2(0, 0);
            for (int j = 0; j < m; j += 4) {
                int eA = j + half, eB = j + 2 + half;
                bool vA = (eA < m), vB = (eB < m);
                int selA = vA ? eA : j, selB = vB ? eB : j;
                int dA = __shfl_sync(0xffffffffu, ent.x, selA);
                float wtA = __int_as_float(__shfl_sync(0xffffffffu, ent.y, selA));
                int dB = __shfl_sync(0xffffffffu, ent.x, selB);
                float wtB = __int_as_float(__shfl_sync(0xffffffffu, ent.y, selB));
                if (!vA) wtA = 0.f;
                if (!vB || j + 2 >= m) wtB = 0.f;
                uint4 nA = __ldg(&nh4[(size_t)dA * 16 + lh]);
                uint4 nB;
                if (j + 2 < m) nB = __ldg(&nh4[(size_t)dB * 16 + lh]);
                float nf[8];
                h8_to_f8(nA, nf);
#pragma unroll
                for (int q = 0; q < 8; q++) acc[q] += wtA * nf[q];
                csum += wtA;
                if (j + 2 < m) {
                    h8_to_f8(nB, nf);
#pragma unroll
                    for (int q = 0; q < 8; q++) acc[q] += wtB * nf[q];
                    csum += wtB;
                }
            }
        }
#pragma unroll
        for (int q = 0; q < 8; q++) acc[q] += __shfl_xor_sync(0xffffffffu, acc[q], 16);
        csum += __shfl_xor_sync(0xffffffffu, csum, 16);

        if (half == 0) {
            float inv = 1.f / fmaxf(csum, 1.0f);
            uint4 o;
            __half2 h;
            h = __floats2half2_rn(acc[0] * inv, acc[1] * inv); o.x = *reinterpret_cast<unsigned*>(&h);
            h = __floats2half2_rn(acc[2] * inv, acc[3] * inv); o.y = *reinterpret_cast<unsigned*>(&h);
            h = __floats2half2_rn(acc[4] * inv, acc[5] * inv); o.z = *reinterpret_cast<unsigned*>(&h);
            h = __floats2half2_rn(acc[6] * inv, acc[7] * inv); o.w = *reinterpret_cast<unsigned*>(&h);
            reinterpret_cast<uint4*>(g_meanh)[(size_t)kk * 16 + lh] = o;
        }
    }
}

// ---------------------------------------------------------------------------
// 4. Final fused GEMM via tensor cores (64x128 tile, 8 warps, 3 phases).
//    All phases read fp16 A (phase 0 uses g_nodeh — bit-identical to the
//    in-kernel conversion it replaces, half the A traffic).
// ---------------------------------------------------------------------------
__global__ __launch_bounds__(256) void final_gemm_mma(const float* __restrict__ W1, const float* __restrict__ b1,
                                                      const float* __restrict__ W2, const float* __restrict__ b2,
                                                      const float* __restrict__ W3, const float* __restrict__ b3,
                                                      float* __restrict__ out, int M) {
    __shared__ __half As[64 * PADK];
    __shared__ __half Bs[128 * PADK];

    const int rowBase = blockIdx.x * 64;
    const int tid = threadIdx.x;
    const int wid = tid >> 5, lane = tid & 31;
    const int m0 = (wid >> 2) * 32;
    const int n0 = (wid & 3) * 32;

    float res[2][4][4];
#pragma unroll
    for (int mt = 0; mt < 2; mt++)
#pragma unroll
        for (int nt = 0; nt < 4; nt++)
#pragma unroll
            for (int q = 0; q < 4; q++) res[mt][nt][q] = 0.f;

    for (int phase = 0; phase < 3; phase++) {
        const float* W = (phase == 0) ? W1 : (phase == 1) ? W2 : W3;
        const float* bb = (phase == 0) ? b1 : (phase == 1) ? b2 : b3;
        const __half* Ah = (phase == 0) ? g_nodeh : (phase == 1) ? g_aggh : g_meanh;

        float c[2][4][4];
#pragma unroll
        for (int mt = 0; mt < 2; mt++)
#pragma unroll
            for (int nt = 0; nt < 4; nt++)
#pragma unroll
                for (int q = 0; q < 4; q++) c[mt][nt][q] = 0.f;

        for (int kb = 0; kb < 128; kb += 64) {
            __syncthreads();
#pragma unroll
            for (int it = 0; it < 4; it++) {
                int idx = tid + it * 256;
                int row = idx >> 4, c4 = (idx & 15) * 4;
                int gr = min(rowBase + row, M - 1);
                uint2 p = *reinterpret_cast<const uint2*>(&Ah[(size_t)gr * DD + kb + c4]);
                *reinterpret_cast<uint2*>(&As[row * PADK + c4]) = p;
            }
#pragma unroll
            for (int it = 0; it < 8; it++) {
                int idx = tid + it * 256;
                int n = idx >> 4, c4 = (idx & 15) * 4;
                float4 w = *reinterpret_cast<const float4*>(&W[(size_t)n * DD + kb + c4]);
                __half2 w01 = __floats2half2_rn(w.x, w.y);
                __half2 w23 = __floats2half2_rn(w.z, w.w);
                uint2 q;
                q.x = *reinterpret_cast<unsigned*>(&w01);
                q.y = *reinterpret_cast<unsigned*>(&w23);
                *reinterpret_cast<uint2*>(&Bs[n * PADK + c4]) = q;
            }
            __syncthreads();

#pragma unroll
            for (int ks = 0; ks < 4; ks++) {
                int k = ks * 16;
                unsigned a[2][4], b[4][2];
#pragma unroll
                for (int mt = 0; mt < 2; mt++) {
                    int r = m0 + mt * 16 + ((lane >> 3) & 1) * 8 + (lane & 7);
                    int cc = k + (lane >> 4) * 8;
                    LDMX4(a[mt][0], a[mt][1], a[mt][2], a[mt][3], smem_u32(&As[r * PADK + cc]));
                }
#pragma unroll
                for (int np = 0; np < 2; np++) {
                    int mat = lane >> 3;
                    int r = n0 + np * 16 + (mat & 2) * 4 + (lane & 7);
                    int cc = k + (mat & 1) * 8;
                    unsigned r0, r1, r2, r3;
                    LDMX4(r0, r1, r2, r3, smem_u32(&Bs[r * PADK + cc]));
                    b[np * 2][0] = r0; b[np * 2][1] = r1;
                    b[np * 2 + 1][0] = r2; b[np * 2 + 1][1] = r3;
                }
#pragma unroll
                for (int mt = 0; mt < 2; mt++)
#pragma unroll
                    for (int nt = 0; nt < 4; nt++) MMA16816(c[mt][nt], a[mt], b[nt]);
            }
        }

#pragma unroll
        for (int mt = 0; mt < 2; mt++)
#pragma unroll
            for (int nt = 0; nt < 4; nt++) {
                int col = n0 + nt * 8 + (lane & 3) * 2;
                float bj0 = bb[col], bj1 = bb[col + 1];
                res[mt][nt][0] += tanhf(c[mt][nt][0] + bj0);
                res[mt][nt][1] += tanhf(c[mt][nt][1] + bj1);
                res[mt][nt][2] += tanhf(c[mt][nt][2] + bj0);
                res[mt][nt][3] += tanhf(c[mt][nt][3] + bj1);
            }
    }

#pragma unroll
    for (int mt = 0; mt < 2; mt++) {
        int row0 = rowBase + m0 + mt * 16 + (lane >> 2);
#pragma unroll
        for (int q = 0; q < 2; q++) {
            int r = row0 + q * 8;
            if (r >= M) continue;
#pragma unroll
            for (int nt = 0; nt < 4; nt++) {
                int col = n0 + nt * 8 + (lane & 3) * 2;
                float2 v = make_float2(res[mt][nt][q * 2 + 0], res[mt][nt][q * 2 + 1]);
                *reinterpret_cast<float2*>(&out[(size_t)r * DD + col]) = v;
            }
        }
    }
}

// ---------------------------------------------------------------------------
// Launcher — fork/join: CSR build (s2) overlaps uv_gemm (main stream)
// ---------------------------------------------------------------------------
extern "C" void kernel_launch(void* const* d_in, const int* in_sizes, int n_in,
                              void* d_out, int out_size) {
    const float* node   = (const float*)d_in[0];
    const int*   er_src = (const int*)d_in[1];
    const int*   er_dst = (const int*)d_in[2];
    const int*   ee_src = (const int*)d_in[3];
    const int*   ee_dst = (const int*)d_in[4];
    const float* ee_w   = (const float*)d_in[5];
    const int*   rr_src = (const int*)d_in[6];
    const int*   rr_dst = (const int*)d_in[7];
    const float* W_attn = (const float*)d_in[8];
    const float* b_attn = (const float*)d_in[9];
    const float* w0_w   = (const float*)d_in[10];
    const float* w0_b   = (const float*)d_in[11];
    const float* W1     = (const float*)d_in[12];
    const float* b1     = (const float*)d_in[13];
    const float* W2     = (const float*)d_in[14];
    const float* b2     = (const float*)d_in[15];
    const float* W3     = (const float*)d_in[16];
    const float* b3     = (const float*)d_in[17];
    float* out = (float*)d_out;

    int N    = in_sizes[0] / DD;
    int E_er = in_sizes[1];
    int E_ee = in_sizes[3];
    int E_rr = in_sizes[6];

    int Etot    = E_er + E_ee + E_rr;
    int totMean = E_er + E_ee + E_rr;      // mean entries (rebased)
    int n2      = 2 * N;
    int nScanBlk = (n2 + SCAN_BS - 1) / SCAN_BS;

    cudaStream_t s2 = g_res.s2;

    cudaEventRecord(g_res.evFork, 0);
    cudaStreamWaitEvent(s2, g_res.evFork, 0);

    // --- s2: CSR build chain ---
    zero_cnt<<<(n2 + 255) / 256, 256, 0, s2>>>(n2);
    count_edges<<<(Etot + 255) / 256, 256, 0, s2>>>(er_src, er_dst, ee_src, rr_src,
                                                    E_er, E_ee, E_rr);
    scan_a<<<nScanBlk, SCAN_BS, 0, s2>>>(n2);
    scan_b<<<1, SCAN_BS, 0, s2>>>(nScanBlk);
    scan_c<<<nScanBlk, SCAN_BS, 0, s2>>>(n2);
    fill_edges<<<(Etot + 255) / 256, 256, 0, s2>>>(er_src, er_dst, ee_src, ee_dst, ee_w,
                                                   rr_src, rr_dst, E_er, E_ee, E_rr);

    // --- main stream: u, v projections (also writes fp16 node copy) ---
    {
        dim3 grid((N + 127) / 128, 2);
        uv_gemm_mma<<<grid, 256>>>(node, W_attn, b_attn, N);
    }

    cudaEventRecord(g_res.evJoin, s2);
    cudaStreamWaitEvent(0, g_res.evJoin, 0);

    // merged gather pass (attn + mean), phase-separated, no atomics
    gather_all<<<(2 * N + 7) / 8, 256>>>(w0_w, w0_b, N, E_er, totMean);
    // final fused 3-phase GEMM (tensor cores), phase-0 A from fp16 node copy
    final_gemm_mma<<<(N + 63) / 64, 256>>>(W1, b1, W2, b2, W3, b3, out, N);
}

// round 12
// speedup vs baseline: 1.2595x; 1.0245x over previous
#include <cuda_runtime.h>
#include <cuda_fp16.h>
#include <math.h>

// ---------------------------------------------------------------------------
// Problem constants
// ---------------------------------------------------------------------------
#define NN 100000
#define DD 128
#define PADK 72        // padded smem row stride (halves), conflict-free ldmatrix
#define MAX_ATTN 850000
#define MAX_MEAN 2100000
#define SCAN_BS 512

// ---------------------------------------------------------------------------
// Scratch (device globals — no allocation allowed)
// ---------------------------------------------------------------------------
__device__ __align__(16) __half g_uvh[(size_t)NN * 256];   // [u(+bias) | v] per node
__device__ __align__(16) __half g_nodeh[(size_t)NN * DD];  // fp16 node_emb
__device__ __align__(16) __half g_aggh[(size_t)NN * DD];   // normalized attn agg
__device__ __align__(16) __half g_meanh[(size_t)NN * DD];  // normalized mean agg
__device__ int   g_csr_cnt[2 * NN];
__device__ int   g_start[2 * NN];   // segment starts (stable)
__device__ int   g_pos[2 * NN];     // fill cursors (mutated by fill)
__device__ int   g_blocksums[SCAN_BS];
__device__ int   g_blockoff[SCAN_BS];
__device__ int   g_aidx[MAX_ATTN];                         // attn CSR entries (dst)
__device__ __align__(8) int2 g_ment[MAX_MEAN];             // mean CSR entries (idx, w-bits)

// ---------------------------------------------------------------------------
// Static stream/event resources
// ---------------------------------------------------------------------------
namespace {
struct StreamRes {
    cudaStream_t s2;
    cudaEvent_t evFork, evJoin, evAttnDone, evMeanDone;
    StreamRes() {
        cudaStreamCreateWithFlags(&s2, cudaStreamNonBlocking);
        cudaEventCreateWithFlags(&evFork, cudaEventDisableTiming);
        cudaEventCreateWithFlags(&evJoin, cudaEventDisableTiming);
        cudaEventCreateWithFlags(&evAttnDone, cudaEventDisableTiming);
        cudaEventCreateWithFlags(&evMeanDone, cudaEventDisableTiming);
    }
};
StreamRes g_res;
}

// ---------------------------------------------------------------------------
// Helpers
// ---------------------------------------------------------------------------
__device__ __forceinline__ __half2 tanh2(__half2 x) {
    __half2 r;
    asm("tanh.approx.f16x2 %0, %1;"
        : "=r"(*reinterpret_cast<unsigned*>(&r))
        : "r"(*reinterpret_cast<const unsigned*>(&x)));
    return r;
}

__device__ __forceinline__ void h8_to_f8(uint4 p, float* f) {
    float2 t;
    t = __half22float2(*reinterpret_cast<__half2*>(&p.x)); f[0] = t.x; f[1] = t.y;
    t = __half22float2(*reinterpret_cast<__half2*>(&p.y)); f[2] = t.x; f[3] = t.y;
    t = __half22float2(*reinterpret_cast<__half2*>(&p.z)); f[4] = t.x; f[5] = t.y;
    t = __half22float2(*reinterpret_cast<__half2*>(&p.w)); f[6] = t.x; f[7] = t.y;
}

__device__ __forceinline__ unsigned smem_u32(const void* p) {
    return (unsigned)__cvta_generic_to_shared(p);
}

#define LDMX4(r0, r1, r2, r3, addr)                                              \
    asm volatile("ldmatrix.sync.aligned.m8n8.x4.shared.b16 {%0,%1,%2,%3}, [%4];" \
                 : "=r"(r0), "=r"(r1), "=r"(r2), "=r"(r3) : "r"(addr))

#define MMA16816(c, a, b)                                                        \
    asm volatile("mma.sync.aligned.m16n8k16.row.col.f32.f16.f16.f32 "            \
                 "{%0,%1,%2,%3}, {%4,%5,%6,%7}, {%8,%9}, {%0,%1,%2,%3};"         \
                 : "+f"((c)[0]), "+f"((c)[1]), "+f"((c)[2]), "+f"((c)[3])        \
                 : "r"((a)[0]), "r"((a)[1]), "r"((a)[2]), "r"((a)[3]),           \
                   "r"((b)[0]), "r"((b)[1]))

// ---------------------------------------------------------------------------
// 0. Zero CSR counters
// ---------------------------------------------------------------------------
__global__ void zero_cnt(int n2) {
    int i = blockIdx.x * blockDim.x + threadIdx.x;
    if (i < n2) g_csr_cnt[i] = 0;
}

// ---------------------------------------------------------------------------
// CSR build: count -> scan -> fill.
// ---------------------------------------------------------------------------
__global__ void count_edges(const int* __restrict__ er_s, const int* __restrict__ er_d,
                            const int* __restrict__ ee_s, const int* __restrict__ rr_s,
                            int Eer, int Eee, int Err) {
    int i = blockIdx.x * blockDim.x + threadIdx.x;
    if (i < Eer) {
        atomicAdd(&g_csr_cnt[er_s[i]], 1);
        atomicAdd(&g_csr_cnt[NN + er_d[i]], 1);
    } else if (i < Eer + Eee) {
        atomicAdd(&g_csr_cnt[NN + ee_s[i - Eer]], 1);
    } else if (i < Eer + Eee + Err) {
        atomicAdd(&g_csr_cnt[NN + rr_s[i - Eer - Eee]], 1);
    }
}

__global__ void scan_a(int n) {
    __shared__ int sh[SCAN_BS];
    int tid = threadIdx.x;
    int i = blockIdx.x * SCAN_BS + tid;
    int v = (i < n) ? g_csr_cnt[i] : 0;
    sh[tid] = v;
    __syncthreads();
    for (int off = 1; off < SCAN_BS; off <<= 1) {
        int t = (tid >= off) ? sh[tid - off] : 0;
        __syncthreads();
        sh[tid] += t;
        __syncthreads();
    }
    if (i < n) g_start[i] = sh[tid] - v;
    if (tid == SCAN_BS - 1) g_blocksums[blockIdx.x] = sh[tid];
}

__global__ void scan_b(int nb) {
    __shared__ int sh[SCAN_BS];
    int tid = threadIdx.x;
    int v = (tid < nb) ? g_blocksums[tid] : 0;
    sh[tid] = v;
    __syncthreads();
    for (int off = 1; off < SCAN_BS; off <<= 1) {
        int t = (tid >= off) ? sh[tid - off] : 0;
        __syncthreads();
        sh[tid] += t;
        __syncthreads();
    }
    if (tid < nb) g_blockoff[tid] = sh[tid] - v;
}

__global__ void scan_c(int n) {
    int i = blockIdx.x * SCAN_BS + threadIdx.x;
    if (i < n) {
        int v = g_start[i] + g_blockoff[blockIdx.x];
        g_start[i] = v;
        g_pos[i] = v;
    }
}

__global__ void fill_edges(const int* __restrict__ er_s, const int* __restrict__ er_d,
                           const int* __restrict__ ee_s, const int* __restrict__ ee_d,
                           const float* __restrict__ ee_w, const int* __restrict__ rr_s,
                           const int* __restrict__ rr_d,
                           int Eer, int Eee, int Err) {
    int i = blockIdx.x * blockDim.x + threadIdx.x;
    const float one = 1.0f;
    if (i < Eer) {
        int s = er_s[i], d = er_d[i];
        int p = atomicAdd(&g_pos[s], 1);
        g_aidx[p] = d;
        int p2 = atomicAdd(&g_pos[NN + d], 1) - Eer;
        g_ment[p2] = make_int2(s, __float_as_int(one));
    } else if (i < Eer + Eee) {
        int j = i - Eer;
        int p = atomicAdd(&g_pos[NN + ee_s[j]], 1) - Eer;
        g_ment[p] = make_int2(ee_d[j], __float_as_int(ee_w[j]));
    } else if (i < Eer + Eee + Err) {
        int j = i - Eer - Eee;
        int p = atomicAdd(&g_pos[NN + rr_s[j]], 1) - Eer;
        g_ment[p] = make_int2(rr_d[j], __float_as_int(one));
    }
}

// ---------------------------------------------------------------------------
// 1. uv projections via tensor cores (128x128 block tile, 8 warps).
//    by 0: u = x@Wr^T + b_attn (also writes fp16 node copy); by 1: v = x@Wh^T.
// ---------------------------------------------------------------------------
__global__ __launch_bounds__(256) void uv_gemm_mma(const float* __restrict__ A,
                                                   const float* __restrict__ W,
                                                   const float* __restrict__ bias,
                                                   int M) {
    __shared__ __half As[128 * PADK];
    __shared__ __half Bs[128 * PADK];

    const int by = blockIdx.y;
    const int rowBase = blockIdx.x * 128;
    const int tid = threadIdx.x;
    const int wid = tid >> 5, lane = tid & 31;
    const int m0 = (wid >> 1) * 32;
    const int n0 = (wid & 1) * 64;
    const float* Wb = W + by * 128;

    float c[2][8][4];
#pragma unroll
    for (int mt = 0; mt < 2; mt++)
#pragma unroll
        for (int nt = 0; nt < 8; nt++)
#pragma unroll
            for (int q = 0; q < 4; q++) c[mt][nt][q] = 0.f;

    for (int kb = 0; kb < 128; kb += 64) {
        __syncthreads();
#pragma unroll
        for (int it = 0; it < 8; it++) {
            int idx = tid + it * 256;
            int row = idx >> 4, c4 = (idx & 15) * 4;
            int grow = rowBase + row;
            int gr = min(grow, M - 1);
            float4 v = *reinterpret_cast<const float4*>(&A[(size_t)gr * DD + kb + c4]);
            __half2 h01 = __floats2half2_rn(v.x, v.y);
            __half2 h23 = __floats2half2_rn(v.z, v.w);
            uint2 p;
            p.x = *reinterpret_cast<unsigned*>(&h01);
            p.y = *reinterpret_cast<unsigned*>(&h23);
            *reinterpret_cast<uint2*>(&As[row * PADK + c4]) = p;
            if (by == 0 && grow < M)
                reinterpret_cast<uint2*>(g_nodeh)[(size_t)grow * 32 + ((kb + c4) >> 2)] = p;

            float4 w = *reinterpret_cast<const float4*>(&Wb[(size_t)row * 256 + kb + c4]);
            __half2 w01 = __floats2half2_rn(w.x, w.y);
            __half2 w23 = __floats2half2_rn(w.z, w.w);
            uint2 q;
            q.x = *reinterpret_cast<unsigned*>(&w01);
            q.y = *reinterpret_cast<unsigned*>(&w23);
            *reinterpret_cast<uint2*>(&Bs[row * PADK + c4]) = q;
        }
        __syncthreads();

#pragma unroll
        for (int ks = 0; ks < 4; ks++) {
            int k = ks * 16;
            unsigned a[2][4], b[8][2];
#pragma unroll
            for (int mt = 0; mt < 2; mt++) {
                int r = m0 + mt * 16 + ((lane >> 3) & 1) * 8 + (lane & 7);
                int cc = k + (lane >> 4) * 8;
                LDMX4(a[mt][0], a[mt][1], a[mt][2], a[mt][3], smem_u32(&As[r * PADK + cc]));
            }
#pragma unroll
            for (int np = 0; np < 4; np++) {
                int mat = lane >> 3;
                int r = n0 + np * 16 + (mat & 2) * 4 + (lane & 7);
                int cc = k + (mat & 1) * 8;
                unsigned r0, r1, r2, r3;
                LDMX4(r0, r1, r2, r3, smem_u32(&Bs[r * PADK + cc]));
                b[np * 2][0] = r0; b[np * 2][1] = r1;
                b[np * 2 + 1][0] = r2; b[np * 2 + 1][1] = r3;
            }
#pragma unroll
            for (int mt = 0; mt < 2; mt++)
#pragma unroll
                for (int nt = 0; nt < 8; nt++) MMA16816(c[mt][nt], a[mt], b[nt]);
        }
    }

#pragma unroll
    for (int mt = 0; mt < 2; mt++) {
        int row0 = rowBase + m0 + mt * 16 + (lane >> 2);
#pragma unroll
        for (int q = 0; q < 2; q++) {
            int r = row0 + q * 8;
            if (r >= M) continue;
#pragma unroll
            for (int nt = 0; nt < 8; nt++) {
                int col = n0 + nt * 8 + (lane & 3) * 2;
                float v0 = c[mt][nt][q * 2 + 0];
                float v1 = c[mt][nt][q * 2 + 1];
                if (by == 0) { v0 += bias[col]; v1 += bias[col + 1]; }
                *reinterpret_cast<__half2*>(&g_uvh[(size_t)r * 256 + by * 128 + col]) =
                    __floats2half2_rn(v0, v1);
            }
        }
    }
}

// ---------------------------------------------------------------------------
// 2a. Attention gather: one warp per node; half-warp per edge, 2 in flight.
// ---------------------------------------------------------------------------
__global__ __launch_bounds__(256) void attn_gather(const float* __restrict__ w0,
                                                   const float* __restrict__ w0b,
                                                   int N, int Eer) {
    int s = blockIdx.x * 8 + (threadIdx.x >> 5);
    int lane = threadIdx.x & 31;
    int lh = lane & 15;
    int half = lane >> 4;
    if (s >= N) return;

    const uint4* uv4 = reinterpret_cast<const uint4*>(g_uvh);
    const uint4* nh4 = reinterpret_cast<const uint4*>(g_nodeh);

    int beg = g_start[s];
    int end = (s == N - 1) ? Eer : g_start[s + 1];

    uint4 vp = __ldg(&uv4[(size_t)s * 32 + 16 + lh]);
    __half2 vh0 = *reinterpret_cast<__half2*>(&vp.x);
    __half2 vh1 = *reinterpret_cast<__half2*>(&vp.y);
    __half2 vh2 = *reinterpret_cast<__half2*>(&vp.z);
    __half2 vh3 = *reinterpret_cast<__half2*>(&vp.w);
    float w[8];
    float4 wa = __ldg(&reinterpret_cast<const float4*>(w0)[2 * lh]);
    float4 wb = __ldg(&reinterpret_cast<const float4*>(w0)[2 * lh + 1]);
    w[0] = wa.x; w[1] = wa.y; w[2] = wa.z; w[3] = wa.w;
    w[4] = wb.x; w[5] = wb.y; w[6] = wb.z; w[7] = wb.w;
    float b0 = __ldg(w0b);

    float acc[8] = {0, 0, 0, 0, 0, 0, 0, 0};
    float ssum = 0.f;

    for (int p = beg; p < end; p += 32) {
        int m = end - p;
        if (m > 32) m = 32;
        int myd = (lane < m) ? __ldg(&g_aidx[p + lane]) : 0;
        for (int j = 0; j < m; j += 4) {
            int eA = j + half, eB = j + 2 + half;
            bool vA = (eA < m), vB = (eB < m);
            int dA = __shfl_sync(0xffffffffu, myd, vA ? eA : j);
            int dB = __shfl_sync(0xffffffffu, myd, vB ? eB : j);
            uint4 uA = __ldg(&uv4[(size_t)dA * 32 + lh]);
            uint4 nA = __ldg(&nh4[(size_t)dA * 16 + lh]);
            uint4 uB, nB;
            if (j + 2 < m) {
                uB = __ldg(&uv4[(size_t)dB * 32 + lh]);
                nB = __ldg(&nh4[(size_t)dB * 16 + lh]);
            }
            __half2 tA0 = tanh2(__hadd2(*reinterpret_cast<__half2*>(&uA.x), vh0));
            __half2 tA1 = tanh2(__hadd2(*reinterpret_cast<__half2*>(&uA.y), vh1));
            __half2 tA2 = tanh2(__hadd2(*reinterpret_cast<__half2*>(&uA.z), vh2));
            __half2 tA3 = tanh2(__hadd2(*reinterpret_cast<__half2*>(&uA.w), vh3));
            float2 a0 = __half22float2(tA0), a1 = __half22float2(tA1);
            float2 a2 = __half22float2(tA2), a3 = __half22float2(tA3);
            float tA = a0.x * w[0] + a0.y * w[1] + a1.x * w[2] + a1.y * w[3]
                     + a2.x * w[4] + a2.y * w[5] + a3.x * w[6] + a3.y * w[7];

            float tB = 0.f;
            if (j + 2 < m) {
                __half2 tB0 = tanh2(__hadd2(*reinterpret_cast<__half2*>(&uB.x), vh0));
                __half2 tB1 = tanh2(__hadd2(*reinterpret_cast<__half2*>(&uB.y), vh1));
                __half2 tB2 = tanh2(__hadd2(*reinterpret_cast<__half2*>(&uB.z), vh2));
                __half2 tB3 = tanh2(__hadd2(*reinterpret_cast<__half2*>(&uB.w), vh3));
                float2 b0f = __half22float2(tB0), b1f = __half22float2(tB1);
                float2 b2f = __half22float2(tB2), b3f = __half22float2(tB3);
                tB = b0f.x * w[0] + b0f.y * w[1] + b1f.x * w[2] + b1f.y * w[3]
                   + b2f.x * w[4] + b2f.y * w[5] + b3f.x * w[6] + b3f.y * w[7];
            }
            tA += __shfl_xor_sync(0xffffffffu, tA, 1);
            tB += __shfl_xor_sync(0xffffffffu, tB, 1);
            tA += __shfl_xor_sync(0xffffffffu, tA, 2);
            tB += __shfl_xor_sync(0xffffffffu, tB, 2);
            tA += __shfl_xor_sync(0xffffffffu, tA, 4);
            tB += __shfl_xor_sync(0xffffffffu, tB, 4);
            tA += __shfl_xor_sync(0xffffffffu, tA, 8);
            tB += __shfl_xor_sync(0xffffffffu, tB, 8);

            float evA = vA ? __expf(tA + b0) : 0.f;
            float nf[8];
            h8_to_f8(nA, nf);
#pragma unroll
            for (int q = 0; q < 8; q++) acc[q] += evA * nf[q];
            ssum += evA;

            if (j + 2 < m) {
                float evB = vB ? __expf(tB + b0) : 0.f;
                h8_to_f8(nB, nf);
#pragma unroll
                for (int q = 0; q < 8; q++) acc[q] += evB * nf[q];
                ssum += evB;
            }
        }
    }
#pragma unroll
    for (int q = 0; q < 8; q++) acc[q] += __shfl_xor_sync(0xffffffffu, acc[q], 16);
    ssum += __shfl_xor_sync(0xffffffffu, ssum, 16);

    if (half == 0) {
        float inv = 1.f / (ssum + 1e-9f);
        uint4 o;
        __half2 h;
        h = __floats2half2_rn(acc[0] * inv, acc[1] * inv); o.x = *reinterpret_cast<unsigned*>(&h);
        h = __floats2half2_rn(acc[2] * inv, acc[3] * inv); o.y = *reinterpret_cast<unsigned*>(&h);
        h = __floats2half2_rn(acc[4] * inv, acc[5] * inv); o.z = *reinterpret_cast<unsigned*>(&h);
        h = __floats2half2_rn(acc[6] * inv, acc[7] * inv); o.w = *reinterpret_cast<unsigned*>(&h);
        reinterpret_cast<uint4*>(g_aggh)[(size_t)s * 16 + lh] = o;
    }
}

// ---------------------------------------------------------------------------
// 2b. Mean gather: one warp per node; half-warp per entry, 2 in flight.
// ---------------------------------------------------------------------------
__global__ __launch_bounds__(256) void mean_gather(int N, int Eer, int totMean) {
    int kk = blockIdx.x * 8 + (threadIdx.x >> 5);
    int lane = threadIdx.x & 31;
    int lh = lane & 15;
    int half = lane >> 4;
    if (kk >= N) return;

    const uint4* nh4 = reinterpret_cast<const uint4*>(g_nodeh);

    int beg = g_start[NN + kk] - Eer;
    int end = ((kk == N - 1) ? totMean : (g_start[NN + kk + 1] - Eer));

    float acc[8] = {0, 0, 0, 0, 0, 0, 0, 0};
    float csum = 0.f;

    for (int p = beg; p < end; p += 32) {
        int m = end - p;
        if (m > 32) m = 32;
        int2 ent = (lane < m) ? __ldg(&g_ment[p + lane]) : make_int2(0, 0);
        for (int j = 0; j < m; j += 4) {
            int eA = j + half, eB = j + 2 + half;
            bool vA = (eA < m), vB = (eB < m);
            int selA = vA ? eA : j, selB = vB ? eB : j;
            int dA = __shfl_sync(0xffffffffu, ent.x, selA);
            float wtA = __int_as_float(__shfl_sync(0xffffffffu, ent.y, selA));
            int dB = __shfl_sync(0xffffffffu, ent.x, selB);
            float wtB = __int_as_float(__shfl_sync(0xffffffffu, ent.y, selB));
            if (!vA) wtA = 0.f;
            if (!vB || j + 2 >= m) wtB = 0.f;
            uint4 nA = __ldg(&nh4[(size_t)dA * 16 + lh]);
            uint4 nB;
            if (j + 2 < m) nB = __ldg(&nh4[(size_t)dB * 16 + lh]);
            float nf[8];
            h8_to_f8(nA, nf);
#pragma unroll
            for (int q = 0; q < 8; q++) acc[q] += wtA * nf[q];
            csum += wtA;
            if (j + 2 < m) {
                h8_to_f8(nB, nf);
#pragma unroll
                for (int q = 0; q < 8; q++) acc[q] += wtB * nf[q];
                csum += wtB;
            }
        }
    }
#pragma unroll
    for (int q = 0; q < 8; q++) acc[q] += __shfl_xor_sync(0xffffffffu, acc[q], 16);
    csum += __shfl_xor_sync(0xffffffffu, csum, 16);

    if (half == 0) {
        float inv = 1.f / fmaxf(csum, 1.0f);
        uint4 o;
        __half2 h;
        h = __floats2half2_rn(acc[0] * inv, acc[1] * inv); o.x = *reinterpret_cast<unsigned*>(&h);
        h = __floats2half2_rn(acc[2] * inv, acc[3] * inv); o.y = *reinterpret_cast<unsigned*>(&h);
        h = __floats2half2_rn(acc[4] * inv, acc[5] * inv); o.z = *reinterpret_cast<unsigned*>(&h);
        h = __floats2half2_rn(acc[6] * inv, acc[7] * inv); o.w = *reinterpret_cast<unsigned*>(&h);
        reinterpret_cast<uint4*>(g_meanh)[(size_t)kk * 16 + lh] = o;
    }
}

// ---------------------------------------------------------------------------
// 4. Final GEMM split in two kernels sharing one body.
//    PH01: phases {nodeh@W1, aggh@W2}, res=0, write out.
//    PH2 : phase  {meanh@W3}, res seeded from out, write out.
// ---------------------------------------------------------------------------
template <int FIRST, int COUNT, bool SEED>
__device__ __forceinline__ void final_gemm_body(const float* W1, const float* b1,
                                                const float* W2, const float* b2,
                                                const float* W3, const float* b3,
                                                float* out, int M) {
    __shared__ __half As[64 * PADK];
    __shared__ __half Bs[128 * PADK];

    const int rowBase = blockIdx.x * 64;
    const int tid = threadIdx.x;
    const int wid = tid >> 5, lane = tid & 31;
    const int m0 = (wid >> 2) * 32;
    const int n0 = (wid & 3) * 32;

    float res[2][4][4];
    if (SEED) {
#pragma unroll
        for (int mt = 0; mt < 2; mt++) {
            int row0 = rowBase + m0 + mt * 16 + (lane >> 2);
#pragma unroll
            for (int q = 0; q < 2; q++) {
                int r = min(row0 + q * 8, M - 1);
#pragma unroll
                for (int nt = 0; nt < 4; nt++) {
                    int col = n0 + nt * 8 + (lane & 3) * 2;
                    float2 v = *reinterpret_cast<const float2*>(&out[(size_t)r * DD + col]);
                    res[mt][nt][q * 2 + 0] = v.x;
                    res[mt][nt][q * 2 + 1] = v.y;
                }
            }
        }
    } else {
#pragma unroll
        for (int mt = 0; mt < 2; mt++)
#pragma unroll
            for (int nt = 0; nt < 4; nt++)
#pragma unroll
                for (int q = 0; q < 4; q++) res[mt][nt][q] = 0.f;
    }

    for (int phase = FIRST; phase < FIRST + COUNT; phase++) {
        const float* W = (phase == 0) ? W1 : (phase == 1) ? W2 : W3;
        const float* bb = (phase == 0) ? b1 : (phase == 1) ? b2 : b3;
        const __half* Ah = (phase == 0) ? g_nodeh : (phase == 1) ? g_aggh : g_meanh;

        float c[2][4][4];
#pragma unroll
        for (int mt = 0; mt < 2; mt++)
#pragma unroll
            for (int nt = 0; nt < 4; nt++)
#pragma unroll
                for (int q = 0; q < 4; q++) c[mt][nt][q] = 0.f;

        for (int kb = 0; kb < 128; kb += 64) {
            __syncthreads();
#pragma unroll
            for (int it = 0; it < 4; it++) {
                int idx = tid + it * 256;
                int row = idx >> 4, c4 = (idx & 15) * 4;
                int gr = min(rowBase + row, M - 1);
                uint2 p = *reinterpret_cast<const uint2*>(&Ah[(size_t)gr * DD + kb + c4]);
                *reinterpret_cast<uint2*>(&As[row * PADK + c4]) = p;
            }
#pragma unroll
            for (int it = 0; it < 8; it++) {
                int idx = tid + it * 256;
                int n = idx >> 4, c4 = (idx & 15) * 4;
                float4 w = *reinterpret_cast<const float4*>(&W[(size_t)n * DD + kb + c4]);
                __half2 w01 = __floats2half2_rn(w.x, w.y);
                __half2 w23 = __floats2half2_rn(w.z, w.w);
                uint2 q;
                q.x = *reinterpret_cast<unsigned*>(&w01);
                q.y = *reinterpret_cast<unsigned*>(&w23);
                *reinterpret_cast<uint2*>(&Bs[n * PADK + c4]) = q;
            }
            __syncthreads();

#pragma unroll
            for (int ks = 0; ks < 4; ks++) {
                int k = ks * 16;
                unsigned a[2][4], b[4][2];
#pragma unroll
                for (int mt = 0; mt < 2; mt++) {
                    int r = m0 + mt * 16 + ((lane >> 3) & 1) * 8 + (lane & 7);
                    int cc = k + (lane >> 4) * 8;
                    LDMX4(a[mt][0], a[mt][1], a[mt][2], a[mt][3], smem_u32(&As[r * PADK + cc]));
                }
#pragma unroll
                for (int np = 0; np < 2; np++) {
                    int mat = lane >> 3;
                    int r = n0 + np * 16 + (mat & 2) * 4 + (lane & 7);
                    int cc = k + (mat & 1) * 8;
                    unsigned r0, r1, r2, r3;
                    LDMX4(r0, r1, r2, r3, smem_u32(&Bs[r * PADK + cc]));
                    b[np * 2][0] = r0; b[np * 2][1] = r1;
                    b[np * 2 + 1][0] = r2; b[np * 2 + 1][1] = r3;
                }
#pragma unroll
                for (int mt = 0; mt < 2; mt++)
#pragma unroll
                    for (int nt = 0; nt < 4; nt++) MMA16816(c[mt][nt], a[mt], b[nt]);
            }
        }

#pragma unroll
        for (int mt = 0; mt < 2; mt++)
#pragma unroll
            for (int nt = 0; nt < 4; nt++) {
                int col = n0 + nt * 8 + (lane & 3) * 2;
                float bj0 = bb[col], bj1 = bb[col + 1];
                res[mt][nt][0] += tanhf(c[mt][nt][0] + bj0);
                res[mt][nt][1] += tanhf(c[mt][nt][1] + bj1);
                res[mt][nt][2] += tanhf(c[mt][nt][2] + bj0);
                res[mt][nt][3] += tanhf(c[mt][nt][3] + bj1);
            }
    }

#pragma unroll
    for (int mt = 0; mt < 2; mt++) {
        int row0 = rowBase + m0 + mt * 16 + (lane >> 2);
#pragma unroll
        for (int q = 0; q < 2; q++) {
            int r = row0 + q * 8;
            if (r >= M) continue;
#pragma unroll
            for (int nt = 0; nt < 4; nt++) {
                int col = n0 + nt * 8 + (lane & 3) * 2;
                float2 v = make_float2(res[mt][nt][q * 2 + 0], res[mt][nt][q * 2 + 1]);
                *reinterpret_cast<float2*>(&out[(size_t)r * DD + col]) = v;
            }
        }
    }
}

__global__ __launch_bounds__(256) void final_gemm_01(const float* __restrict__ W1, const float* __restrict__ b1,
                                                     const float* __restrict__ W2, const float* __restrict__ b2,
                                                     float* __restrict__ out, int M) {
    final_gemm_body<0, 2, false>(W1, b1, W2, b2, nullptr, nullptr, out, M);
}

__global__ __launch_bounds__(256) void final_gemm_2(const float* __restrict__ W3, const float* __restrict__ b3,
                                                    float* __restrict__ out, int M) {
    final_gemm_body<2, 1, true>(nullptr, nullptr, nullptr, nullptr, W3, b3, out, M);
}

// ---------------------------------------------------------------------------
// Launcher — fork/join pipeline:
//   s2:   CSR chain ............ mean_gather (after attn done) ...
//   main: uv_gemm .. attn_gather .. gemm01 (|| mean_gather) .. gemm2
// ---------------------------------------------------------------------------
extern "C" void kernel_launch(void* const* d_in, const int* in_sizes, int n_in,
                              void* d_out, int out_size) {
    const float* node   = (const float*)d_in[0];
    const int*   er_src = (const int*)d_in[1];
    const int*   er_dst = (const int*)d_in[2];
    const int*   ee_src = (const int*)d_in[3];
    const int*   ee_dst = (const int*)d_in[4];
    const float* ee_w   = (const float*)d_in[5];
    const int*   rr_src = (const int*)d_in[6];
    const int*   rr_dst = (const int*)d_in[7];
    const float* W_attn = (const float*)d_in[8];
    const float* b_attn = (const float*)d_in[9];
    const float* w0_w   = (const float*)d_in[10];
    const float* w0_b   = (const float*)d_in[11];
    const float* W1     = (const float*)d_in[12];
    const float* b1     = (const float*)d_in[13];
    const float* W2     = (const float*)d_in[14];
    const float* b2     = (const float*)d_in[15];
    const float* W3     = (const float*)d_in[16];
    const float* b3     = (const float*)d_in[17];
    float* out = (float*)d_out;

    int N    = in_sizes[0] / DD;
    int E_er = in_sizes[1];
    int E_ee = in_sizes[3];
    int E_rr = in_sizes[6];

    int Etot    = E_er + E_ee + E_rr;
    int totMean = E_er + E_ee + E_rr;      // mean entries (rebased)
    int n2      = 2 * N;
    int nScanBlk = (n2 + SCAN_BS - 1) / SCAN_BS;

    cudaStream_t s2 = g_res.s2;

    cudaEventRecord(g_res.evFork, 0);
    cudaStreamWaitEvent(s2, g_res.evFork, 0);

    // --- s2: CSR build chain ---
    zero_cnt<<<(n2 + 255) / 256, 256, 0, s2>>>(n2);
    count_edges<<<(Etot + 255) / 256, 256, 0, s2>>>(er_src, er_dst, ee_src, rr_src,
                                                    E_er, E_ee, E_rr);
    scan_a<<<nScanBlk, SCAN_BS, 0, s2>>>(n2);
    scan_b<<<1, SCAN_BS, 0, s2>>>(nScanBlk);
    scan_c<<<nScanBlk, SCAN_BS, 0, s2>>>(n2);
    fill_edges<<<(Etot + 255) / 256, 256, 0, s2>>>(er_src, er_dst, ee_src, ee_dst, ee_w,
                                                   rr_src, rr_dst, E_er, E_ee, E_rr);

    // --- main stream: u, v projections (also writes fp16 node copy) ---
    {
        dim3 grid((N + 127) / 128, 2);
        uv_gemm_mma<<<grid, 256>>>(node, W_attn, b_attn, N);
    }

    // join CSR -> main, then attn gather on main
    cudaEventRecord(g_res.evJoin, s2);
    cudaStreamWaitEvent(0, g_res.evJoin, 0);
    attn_gather<<<(N + 7) / 8, 256>>>(w0_w, w0_b, N, E_er);

    // fork: mean gather on s2 (ordered after attn via event, so no cache clash
    // with attn; overlaps with gemm01 on main)
    cudaEventRecord(g_res.evAttnDone, 0);
    cudaStreamWaitEvent(s2, g_res.evAttnDone, 0);
    mean_gather<<<(N + 7) / 8, 256, 0, s2>>>(N, E_er, totMean);

    // main: phases 0-1 of the output GEMM (needs nodeh + aggh only)
    final_gemm_01<<<(N + 63) / 64, 256>>>(W1, b1, W2, b2, out, N);

    // join mean gather -> main, then phase 2 accumulate
    cudaEventRecord(g_res.evMeanDone, s2);
    cudaStreamWaitEvent(0, g_res.evMeanDone, 0);
    final_gemm_2<<<(N + 63) / 64, 256>>>(W3, b3, out, N);
}

// round 13
// speedup vs baseline: 1.2870x; 1.0218x over previous
#include <cuda_runtime.h>
#include <cuda_fp16.h>
#include <math.h>

// ---------------------------------------------------------------------------
// Problem constants
// ---------------------------------------------------------------------------
#define NN 100000
#define DD 128
#define PADK 72        // padded smem row stride (halves), conflict-free ldmatrix
#define MAX_ATTN 850000
#define MAX_MEAN 2100000
#define SCAN_BS 512

// ---------------------------------------------------------------------------
// Scratch (device globals — no allocation allowed)
// ---------------------------------------------------------------------------
__device__ __align__(16) __half g_uvh[(size_t)NN * 256];   // [u(+bias) | v] per node
__device__ __align__(16) __half g_nodeh[(size_t)NN * DD];  // fp16 node_emb
__device__ __align__(16) __half g_aggh[(size_t)NN * DD];   // normalized attn agg
__device__ __align__(16) __half g_meanh[(size_t)NN * DD];  // normalized mean agg
__device__ int   g_csr_cnt[2 * NN];
__device__ int   g_start[2 * NN];   // segment starts (stable)
__device__ int   g_pos[2 * NN];     // fill cursors (mutated by fill)
__device__ int   g_blocksums[SCAN_BS];
__device__ int   g_blockoff[SCAN_BS];
__device__ int   g_aidx[MAX_ATTN];                         // attn CSR entries (dst)
__device__ __align__(8) int2 g_ment[MAX_MEAN];             // mean CSR entries (idx, w-bits)

// ---------------------------------------------------------------------------
// Static stream/event resources
// ---------------------------------------------------------------------------
namespace {
struct StreamRes {
    cudaStream_t s2;
    cudaEvent_t evFork, evCsrDone, evUvDone, evMeanDone;
    StreamRes() {
        cudaStreamCreateWithFlags(&s2, cudaStreamNonBlocking);
        cudaEventCreateWithFlags(&evFork, cudaEventDisableTiming);
        cudaEventCreateWithFlags(&evCsrDone, cudaEventDisableTiming);
        cudaEventCreateWithFlags(&evUvDone, cudaEventDisableTiming);
        cudaEventCreateWithFlags(&evMeanDone, cudaEventDisableTiming);
    }
};
StreamRes g_res;
}

// ---------------------------------------------------------------------------
// Helpers
// ---------------------------------------------------------------------------
__device__ __forceinline__ __half2 tanh2(__half2 x) {
    __half2 r;
    asm("tanh.approx.f16x2 %0, %1;"
        : "=r"(*reinterpret_cast<unsigned*>(&r))
        : "r"(*reinterpret_cast<const unsigned*>(&x)));
    return r;
}

__device__ __forceinline__ void h8_to_f8(uint4 p, float* f) {
    float2 t;
    t = __half22float2(*reinterpret_cast<__half2*>(&p.x)); f[0] = t.x; f[1] = t.y;
    t = __half22float2(*reinterpret_cast<__half2*>(&p.y)); f[2] = t.x; f[3] = t.y;
    t = __half22float2(*reinterpret_cast<__half2*>(&p.z)); f[4] = t.x; f[5] = t.y;
    t = __half22float2(*reinterpret_cast<__half2*>(&p.w)); f[6] = t.x; f[7] = t.y;
}

__device__ __forceinline__ unsigned smem_u32(const void* p) {
    return (unsigned)__cvta_generic_to_shared(p);
}

#define LDMX4(r0, r1, r2, r3, addr)                                              \
    asm volatile("ldmatrix.sync.aligned.m8n8.x4.shared.b16 {%0,%1,%2,%3}, [%4];" \
                 : "=r"(r0), "=r"(r1), "=r"(r2), "=r"(r3) : "r"(addr))

#define MMA16816(c, a, b)                                                        \
    asm volatile("mma.sync.aligned.m16n8k16.row.col.f32.f16.f16.f32 "            \
                 "{%0,%1,%2,%3}, {%4,%5,%6,%7}, {%8,%9}, {%0,%1,%2,%3};"         \
                 : "+f"((c)[0]), "+f"((c)[1]), "+f"((c)[2]), "+f"((c)[3])        \
                 : "r"((a)[0]), "r"((a)[1]), "r"((a)[2]), "r"((a)[3]),           \
                   "r"((b)[0]), "r"((b)[1]))

// ---------------------------------------------------------------------------
// 0. Zero CSR counters
// ---------------------------------------------------------------------------
__global__ void zero_cnt(int n2) {
    int i = blockIdx.x * blockDim.x + threadIdx.x;
    if (i < n2) g_csr_cnt[i] = 0;
}

// ---------------------------------------------------------------------------
// CSR build: count -> scan -> fill.
// ---------------------------------------------------------------------------
__global__ void count_edges(const int* __restrict__ er_s, const int* __restrict__ er_d,
                            const int* __restrict__ ee_s, const int* __restrict__ rr_s,
                            int Eer, int Eee, int Err) {
    int i = blockIdx.x * blockDim.x + threadIdx.x;
    if (i < Eer) {
        atomicAdd(&g_csr_cnt[er_s[i]], 1);
        atomicAdd(&g_csr_cnt[NN + er_d[i]], 1);
    } else if (i < Eer + Eee) {
        atomicAdd(&g_csr_cnt[NN + ee_s[i - Eer]], 1);
    } else if (i < Eer + Eee + Err) {
        atomicAdd(&g_csr_cnt[NN + rr_s[i - Eer - Eee]], 1);
    }
}

__global__ void scan_a(int n) {
    __shared__ int sh[SCAN_BS];
    int tid = threadIdx.x;
    int i = blockIdx.x * SCAN_BS + tid;
    int v = (i < n) ? g_csr_cnt[i] : 0;
    sh[tid] = v;
    __syncthreads();
    for (int off = 1; off < SCAN_BS; off <<= 1) {
        int t = (tid >= off) ? sh[tid - off] : 0;
        __syncthreads();
        sh[tid] += t;
        __syncthreads();
    }
    if (i < n) g_start[i] = sh[tid] - v;
    if (tid == SCAN_BS - 1) g_blocksums[blockIdx.x] = sh[tid];
}

__global__ void scan_b(int nb) {
    __shared__ int sh[SCAN_BS];
    int tid = threadIdx.x;
    int v = (tid < nb) ? g_blocksums[tid] : 0;
    sh[tid] = v;
    __syncthreads();
    for (int off = 1; off < SCAN_BS; off <<= 1) {
        int t = (tid >= off) ? sh[tid - off] : 0;
        __syncthreads();
        sh[tid] += t;
        __syncthreads();
    }
    if (tid < nb) g_blockoff[tid] = sh[tid] - v;
}

__global__ void scan_c(int n) {
    int i = blockIdx.x * SCAN_BS + threadIdx.x;
    if (i < n) {
        int v = g_start[i] + g_blockoff[blockIdx.x];
        g_start[i] = v;
        g_pos[i] = v;
    }
}

__global__ void fill_edges(const int* __restrict__ er_s, const int* __restrict__ er_d,
                           const int* __restrict__ ee_s, const int* __restrict__ ee_d,
                           const float* __restrict__ ee_w, const int* __restrict__ rr_s,
                           const int* __restrict__ rr_d,
                           int Eer, int Eee, int Err) {
    int i = blockIdx.x * blockDim.x + threadIdx.x;
    const float one = 1.0f;
    if (i < Eer) {
        int s = er_s[i], d = er_d[i];
        int p = atomicAdd(&g_pos[s], 1);
        g_aidx[p] = d;
        int p2 = atomicAdd(&g_pos[NN + d], 1) - Eer;
        g_ment[p2] = make_int2(s, __float_as_int(one));
    } else if (i < Eer + Eee) {
        int j = i - Eer;
        int p = atomicAdd(&g_pos[NN + ee_s[j]], 1) - Eer;
        g_ment[p] = make_int2(ee_d[j], __float_as_int(ee_w[j]));
    } else if (i < Eer + Eee + Err) {
        int j = i - Eer - Eee;
        int p = atomicAdd(&g_pos[NN + rr_s[j]], 1) - Eer;
        g_ment[p] = make_int2(rr_d[j], __float_as_int(one));
    }
}

// ---------------------------------------------------------------------------
// 1. uv projections via tensor cores (128x128 block tile, 8 warps).
//    by 0: u = x@Wr^T + b_attn (also writes fp16 node copy); by 1: v = x@Wh^T.
// ---------------------------------------------------------------------------
__global__ __launch_bounds__(256) void uv_gemm_mma(const float* __restrict__ A,
                                                   const float* __restrict__ W,
                                                   const float* __restrict__ bias,
                                                   int M) {
    __shared__ __half As[128 * PADK];
    __shared__ __half Bs[128 * PADK];

    const int by = blockIdx.y;
    const int rowBase = blockIdx.x * 128;
    const int tid = threadIdx.x;
    const int wid = tid >> 5, lane = tid & 31;
    const int m0 = (wid >> 1) * 32;
    const int n0 = (wid & 1) * 64;
    const float* Wb = W + by * 128;

    float c[2][8][4];
#pragma unroll
    for (int mt = 0; mt < 2; mt++)
#pragma unroll
        for (int nt = 0; nt < 8; nt++)
#pragma unroll
            for (int q = 0; q < 4; q++) c[mt][nt][q] = 0.f;

    for (int kb = 0; kb < 128; kb += 64) {
        __syncthreads();
#pragma unroll
        for (int it = 0; it < 8; it++) {
            int idx = tid + it * 256;
            int row = idx >> 4, c4 = (idx & 15) * 4;
            int grow = rowBase + row;
            int gr = min(grow, M - 1);
            float4 v = *reinterpret_cast<const float4*>(&A[(size_t)gr * DD + kb + c4]);
            __half2 h01 = __floats2half2_rn(v.x, v.y);
            __half2 h23 = __floats2half2_rn(v.z, v.w);
            uint2 p;
            p.x = *reinterpret_cast<unsigned*>(&h01);
            p.y = *reinterpret_cast<unsigned*>(&h23);
            *reinterpret_cast<uint2*>(&As[row * PADK + c4]) = p;
            if (by == 0 && grow < M)
                reinterpret_cast<uint2*>(g_nodeh)[(size_t)grow * 32 + ((kb + c4) >> 2)] = p;

            float4 w = *reinterpret_cast<const float4*>(&Wb[(size_t)row * 256 + kb + c4]);
            __half2 w01 = __floats2half2_rn(w.x, w.y);
            __half2 w23 = __floats2half2_rn(w.z, w.w);
            uint2 q;
            q.x = *reinterpret_cast<unsigned*>(&w01);
            q.y = *reinterpret_cast<unsigned*>(&w23);
            *reinterpret_cast<uint2*>(&Bs[row * PADK + c4]) = q;
        }
        __syncthreads();

#pragma unroll
        for (int ks = 0; ks < 4; ks++) {
            int k = ks * 16;
            unsigned a[2][4], b[8][2];
#pragma unroll
            for (int mt = 0; mt < 2; mt++) {
                int r = m0 + mt * 16 + ((lane >> 3) & 1) * 8 + (lane & 7);
                int cc = k + (lane >> 4) * 8;
                LDMX4(a[mt][0], a[mt][1], a[mt][2], a[mt][3], smem_u32(&As[r * PADK + cc]));
            }
#pragma unroll
            for (int np = 0; np < 4; np++) {
                int mat = lane >> 3;
                int r = n0 + np * 16 + (mat & 2) * 4 + (lane & 7);
                int cc = k + (mat & 1) * 8;
                unsigned r0, r1, r2, r3;
                LDMX4(r0, r1, r2, r3, smem_u32(&Bs[r * PADK + cc]));
                b[np * 2][0] = r0; b[np * 2][1] = r1;
                b[np * 2 + 1][0] = r2; b[np * 2 + 1][1] = r3;
            }
#pragma unroll
            for (int mt = 0; mt < 2; mt++)
#pragma unroll
                for (int nt = 0; nt < 8; nt++) MMA16816(c[mt][nt], a[mt], b[nt]);
        }
    }

#pragma unroll
    for (int mt = 0; mt < 2; mt++) {
        int row0 = rowBase + m0 + mt * 16 + (lane >> 2);
#pragma unroll
        for (int q = 0; q < 2; q++) {
            int r = row0 + q * 8;
            if (r >= M) continue;
#pragma unroll
            for (int nt = 0; nt < 8; nt++) {
                int col = n0 + nt * 8 + (lane & 3) * 2;
                float v0 = c[mt][nt][q * 2 + 0];
                float v1 = c[mt][nt][q * 2 + 1];
                if (by == 0) { v0 += bias[col]; v1 += bias[col + 1]; }
                *reinterpret_cast<__half2*>(&g_uvh[(size_t)r * 256 + by * 128 + col]) =
                    __floats2half2_rn(v0, v1);
            }
        }
    }
}

// ---------------------------------------------------------------------------
// 2a. Attention gather: one warp per node; half-warp per edge, 2 in flight.
// ---------------------------------------------------------------------------
__global__ __launch_bounds__(256) void attn_gather(const float* __restrict__ w0,
                                                   const float* __restrict__ w0b,
                                                   int N, int Eer) {
    int s = blockIdx.x * 8 + (threadIdx.x >> 5);
    int lane = threadIdx.x & 31;
    int lh = lane & 15;
    int half = lane >> 4;
    if (s >= N) return;

    const uint4* uv4 = reinterpret_cast<const uint4*>(g_uvh);
    const uint4* nh4 = reinterpret_cast<const uint4*>(g_nodeh);

    int beg = g_start[s];
    int end = (s == N - 1) ? Eer : g_start[s + 1];

    uint4 vp = __ldg(&uv4[(size_t)s * 32 + 16 + lh]);
    __half2 vh0 = *reinterpret_cast<__half2*>(&vp.x);
    __half2 vh1 = *reinterpret_cast<__half2*>(&vp.y);
    __half2 vh2 = *reinterpret_cast<__half2*>(&vp.z);
    __half2 vh3 = *reinterpret_cast<__half2*>(&vp.w);
    float w[8];
    float4 wa = __ldg(&reinterpret_cast<const float4*>(w0)[2 * lh]);
    float4 wb = __ldg(&reinterpret_cast<const float4*>(w0)[2 * lh + 1]);
    w[0] = wa.x; w[1] = wa.y; w[2] = wa.z; w[3] = wa.w;
    w[4] = wb.x; w[5] = wb.y; w[6] = wb.z; w[7] = wb.w;
    float b0 = __ldg(w0b);

    float acc[8] = {0, 0, 0, 0, 0, 0, 0, 0};
    float ssum = 0.f;

    for (int p = beg; p < end; p += 32) {
        int m = end - p;
        if (m > 32) m = 32;
        int myd = (lane < m) ? __ldg(&g_aidx[p + lane]) : 0;
        for (int j = 0; j < m; j += 4) {
            int eA = j + half, eB = j + 2 + half;
            bool vA = (eA < m), vB = (eB < m);
            int dA = __shfl_sync(0xffffffffu, myd, vA ? eA : j);
            int dB = __shfl_sync(0xffffffffu, myd, vB ? eB : j);
            uint4 uA = __ldg(&uv4[(size_t)dA * 32 + lh]);
            uint4 nA = __ldg(&nh4[(size_t)dA * 16 + lh]);
            uint4 uB, nB;
            if (j + 2 < m) {
                uB = __ldg(&uv4[(size_t)dB * 32 + lh]);
                nB = __ldg(&nh4[(size_t)dB * 16 + lh]);
            }
            __half2 tA0 = tanh2(__hadd2(*reinterpret_cast<__half2*>(&uA.x), vh0));
            __half2 tA1 = tanh2(__hadd2(*reinterpret_cast<__half2*>(&uA.y), vh1));
            __half2 tA2 = tanh2(__hadd2(*reinterpret_cast<__half2*>(&uA.z), vh2));
            __half2 tA3 = tanh2(__hadd2(*reinterpret_cast<__half2*>(&uA.w), vh3));
            float2 a0 = __half22float2(tA0), a1 = __half22float2(tA1);
            float2 a2 = __half22float2(tA2), a3 = __half22float2(tA3);
            float tA = a0.x * w[0] + a0.y * w[1] + a1.x * w[2] + a1.y * w[3]
                     + a2.x * w[4] + a2.y * w[5] + a3.x * w[6] + a3.y * w[7];

            float tB = 0.f;
            if (j + 2 < m) {
                __half2 tB0 = tanh2(__hadd2(*reinterpret_cast<__half2*>(&uB.x), vh0));
                __half2 tB1 = tanh2(__hadd2(*reinterpret_cast<__half2*>(&uB.y), vh1));
                __half2 tB2 = tanh2(__hadd2(*reinterpret_cast<__half2*>(&uB.z), vh2));
                __half2 tB3 = tanh2(__hadd2(*reinterpret_cast<__half2*>(&uB.w), vh3));
                float2 b0f = __half22float2(tB0), b1f = __half22float2(tB1);
                float2 b2f = __half22float2(tB2), b3f = __half22float2(tB3);
                tB = b0f.x * w[0] + b0f.y * w[1] + b1f.x * w[2] + b1f.y * w[3]
                   + b2f.x * w[4] + b2f.y * w[5] + b3f.x * w[6] + b3f.y * w[7];
            }
            tA += __shfl_xor_sync(0xffffffffu, tA, 1);
            tB += __shfl_xor_sync(0xffffffffu, tB, 1);
            tA += __shfl_xor_sync(0xffffffffu, tA, 2);
            tB += __shfl_xor_sync(0xffffffffu, tB, 2);
            tA += __shfl_xor_sync(0xffffffffu, tA, 4);
            tB += __shfl_xor_sync(0xffffffffu, tB, 4);
            tA += __shfl_xor_sync(0xffffffffu, tA, 8);
            tB += __shfl_xor_sync(0xffffffffu, tB, 8);

            float evA = vA ? __expf(tA + b0) : 0.f;
            float nf[8];
            h8_to_f8(nA, nf);
#pragma unroll
            for (int q = 0; q < 8; q++) acc[q] += evA * nf[q];
            ssum += evA;

            if (j + 2 < m) {
                float evB = vB ? __expf(tB + b0) : 0.f;
                h8_to_f8(nB, nf);
#pragma unroll
                for (int q = 0; q < 8; q++) acc[q] += evB * nf[q];
                ssum += evB;
            }
        }
    }
#pragma unroll
    for (int q = 0; q < 8; q++) acc[q] += __shfl_xor_sync(0xffffffffu, acc[q], 16);
    ssum += __shfl_xor_sync(0xffffffffu, ssum, 16);

    if (half == 0) {
        float inv = 1.f / (ssum + 1e-9f);
        uint4 o;
        __half2 h;
        h = __floats2half2_rn(acc[0] * inv, acc[1] * inv); o.x = *reinterpret_cast<unsigned*>(&h);
        h = __floats2half2_rn(acc[2] * inv, acc[3] * inv); o.y = *reinterpret_cast<unsigned*>(&h);
        h = __floats2half2_rn(acc[4] * inv, acc[5] * inv); o.z = *reinterpret_cast<unsigned*>(&h);
        h = __floats2half2_rn(acc[6] * inv, acc[7] * inv); o.w = *reinterpret_cast<unsigned*>(&h);
        reinterpret_cast<uint4*>(g_aggh)[(size_t)s * 16 + lh] = o;
    }
}

// ---------------------------------------------------------------------------
// 2b. Mean gather: one warp per node; half-warp per entry, 2 in flight.
// ---------------------------------------------------------------------------
__global__ __launch_bounds__(256) void mean_gather(int N, int Eer, int totMean) {
    int kk = blockIdx.x * 8 + (threadIdx.x >> 5);
    int lane = threadIdx.x & 31;
    int lh = lane & 15;
    int half = lane >> 4;
    if (kk >= N) return;

    const uint4* nh4 = reinterpret_cast<const uint4*>(g_nodeh);

    int beg = g_start[NN + kk] - Eer;
    int end = ((kk == N - 1) ? totMean : (g_start[NN + kk + 1] - Eer));

    float acc[8] = {0, 0, 0, 0, 0, 0, 0, 0};
    float csum = 0.f;

    for (int p = beg; p < end; p += 32) {
        int m = end - p;
        if (m > 32) m = 32;
        int2 ent = (lane < m) ? __ldg(&g_ment[p + lane]) : make_int2(0, 0);
        for (int j = 0; j < m; j += 4) {
            int eA = j + half, eB = j + 2 + half;
            bool vA = (eA < m), vB = (eB < m);
            int selA = vA ? eA : j, selB = vB ? eB : j;
            int dA = __shfl_sync(0xffffffffu, ent.x, selA);
            float wtA = __int_as_float(__shfl_sync(0xffffffffu, ent.y, selA));
            int dB = __shfl_sync(0xffffffffu, ent.x, selB);
            float wtB = __int_as_float(__shfl_sync(0xffffffffu, ent.y, selB));
            if (!vA) wtA = 0.f;
            if (!vB || j + 2 >= m) wtB = 0.f;
            uint4 nA = __ldg(&nh4[(size_t)dA * 16 + lh]);
            uint4 nB;
            if (j + 2 < m) nB = __ldg(&nh4[(size_t)dB * 16 + lh]);
            float nf[8];
            h8_to_f8(nA, nf);
#pragma unroll
            for (int q = 0; q < 8; q++) acc[q] += wtA * nf[q];
            csum += wtA;
            if (j + 2 < m) {
                h8_to_f8(nB, nf);
#pragma unroll
                for (int q = 0; q < 8; q++) acc[q] += wtB * nf[q];
                csum += wtB;
            }
        }
    }
#pragma unroll
    for (int q = 0; q < 8; q++) acc[q] += __shfl_xor_sync(0xffffffffu, acc[q], 16);
    csum += __shfl_xor_sync(0xffffffffu, csum, 16);

    if (half == 0) {
        float inv = 1.f / fmaxf(csum, 1.0f);
        uint4 o;
        __half2 h;
        h = __floats2half2_rn(acc[0] * inv, acc[1] * inv); o.x = *reinterpret_cast<unsigned*>(&h);
        h = __floats2half2_rn(acc[2] * inv, acc[3] * inv); o.y = *reinterpret_cast<unsigned*>(&h);
        h = __floats2half2_rn(acc[4] * inv, acc[5] * inv); o.z = *reinterpret_cast<unsigned*>(&h);
        h = __floats2half2_rn(acc[6] * inv, acc[7] * inv); o.w = *reinterpret_cast<unsigned*>(&h);
        reinterpret_cast<uint4*>(g_meanh)[(size_t)kk * 16 + lh] = o;
    }
}

// ---------------------------------------------------------------------------
// 4. Final GEMM split in two kernels sharing one body.
//    PH01: phases {nodeh@W1, aggh@W2}, res=0, write out.
//    PH2 : phase  {meanh@W3}, res seeded from out, write out.
// ---------------------------------------------------------------------------
template <int FIRST, int COUNT, bool SEED>
__device__ __forceinline__ void final_gemm_body(const float* W1, const float* b1,
                                                const float* W2, const float* b2,
                                                const float* W3, const float* b3,
                                                float* out, int M) {
    __shared__ __half As[64 * PADK];
    __shared__ __half Bs[128 * PADK];

    const int rowBase = blockIdx.x * 64;
    const int tid = threadIdx.x;
    const int wid = tid >> 5, lane = tid & 31;
    const int m0 = (wid >> 2) * 32;
    const int n0 = (wid & 3) * 32;

    float res[2][4][4];
    if (SEED) {
#pragma unroll
        for (int mt = 0; mt < 2; mt++) {
            int row0 = rowBase + m0 + mt * 16 + (lane >> 2);
#pragma unroll
            for (int q = 0; q < 2; q++) {
                int r = min(row0 + q * 8, M - 1);
#pragma unroll
                for (int nt = 0; nt < 4; nt++) {
                    int col = n0 + nt * 8 + (lane & 3) * 2;
                    float2 v = *reinterpret_cast<const float2*>(&out[(size_t)r * DD + col]);
                    res[mt][nt][q * 2 + 0] = v.x;
                    res[mt][nt][q * 2 + 1] = v.y;
                }
            }
        }
    } else {
#pragma unroll
        for (int mt = 0; mt < 2; mt++)
#pragma unroll
            for (int nt = 0; nt < 4; nt++)
#pragma unroll
                for (int q = 0; q < 4; q++) res[mt][nt][q] = 0.f;
    }

    for (int phase = FIRST; phase < FIRST + COUNT; phase++) {
        const float* W = (phase == 0) ? W1 : (phase == 1) ? W2 : W3;
        const float* bb = (phase == 0) ? b1 : (phase == 1) ? b2 : b3;
        const __half* Ah = (phase == 0) ? g_nodeh : (phase == 1) ? g_aggh : g_meanh;

        float c[2][4][4];
#pragma unroll
        for (int mt = 0; mt < 2; mt++)
#pragma unroll
            for (int nt = 0; nt < 4; nt++)
#pragma unroll
                for (int q = 0; q < 4; q++) c[mt][nt][q] = 0.f;

        for (int kb = 0; kb < 128; kb += 64) {
            __syncthreads();
#pragma unroll
            for (int it = 0; it < 4; it++) {
                int idx = tid + it * 256;
                int row = idx >> 4, c4 = (idx & 15) * 4;
                int gr = min(rowBase + row, M - 1);
                uint2 p = *reinterpret_cast<const uint2*>(&Ah[(size_t)gr * DD + kb + c4]);
                *reinterpret_cast<uint2*>(&As[row * PADK + c4]) = p;
            }
#pragma unroll
            for (int it = 0; it < 8; it++) {
                int idx = tid + it * 256;
                int n = idx >> 4, c4 = (idx & 15) * 4;
                float4 w = *reinterpret_cast<const float4*>(&W[(size_t)n * DD + kb + c4]);
                __half2 w01 = __floats2half2_rn(w.x, w.y);
                __half2 w23 = __floats2half2_rn(w.z, w.w);
                uint2 q;
                q.x = *reinterpret_cast<unsigned*>(&w01);
                q.y = *reinterpret_cast<unsigned*>(&w23);
                *reinterpret_cast<uint2*>(&Bs[n * PADK + c4]) = q;
            }
            __syncthreads();

#pragma unroll
            for (int ks = 0; ks < 4; ks++) {
                int k = ks * 16;
                unsigned a[2][4], b[4][2];
#pragma unroll
                for (int mt = 0; mt < 2; mt++) {
                    int r = m0 + mt * 16 + ((lane >> 3) & 1) * 8 + (lane & 7);
                    int cc = k + (lane >> 4) * 8;
                    LDMX4(a[mt][0], a[mt][1], a[mt][2], a[mt][3], smem_u32(&As[r * PADK + cc]));
                }
#pragma unroll
                for (int np = 0; np < 2; np++) {
                    int mat = lane >> 3;
                    int r = n0 + np * 16 + (mat & 2) * 4 + (lane & 7);
                    int cc = k + (mat & 1) * 8;
                    unsigned r0, r1, r2, r3;
                    LDMX4(r0, r1, r2, r3, smem_u32(&Bs[r * PADK + cc]));
                    b[np * 2][0] = r0; b[np * 2][1] = r1;
                    b[np * 2 + 1][0] = r2; b[np * 2 + 1][1] = r3;
                }
#pragma unroll
                for (int mt = 0; mt < 2; mt++)
#pragma unroll
                    for (int nt = 0; nt < 4; nt++) MMA16816(c[mt][nt], a[mt], b[nt]);
            }
        }

#pragma unroll
        for (int mt = 0; mt < 2; mt++)
#pragma unroll
            for (int nt = 0; nt < 4; nt++) {
                int col = n0 + nt * 8 + (lane & 3) * 2;
                float bj0 = bb[col], bj1 = bb[col + 1];
                res[mt][nt][0] += tanhf(c[mt][nt][0] + bj0);
                res[mt][nt][1] += tanhf(c[mt][nt][1] + bj1);
                res[mt][nt][2] += tanhf(c[mt][nt][2] + bj0);
                res[mt][nt][3] += tanhf(c[mt][nt][3] + bj1);
            }
    }

#pragma unroll
    for (int mt = 0; mt < 2; mt++) {
        int row0 = rowBase + m0 + mt * 16 + (lane >> 2);
#pragma unroll
        for (int q = 0; q < 2; q++) {
            int r = row0 + q * 8;
            if (r >= M) continue;
#pragma unroll
            for (int nt = 0; nt < 4; nt++) {
                int col = n0 + nt * 8 + (lane & 3) * 2;
                float2 v = make_float2(res[mt][nt][q * 2 + 0], res[mt][nt][q * 2 + 1]);
                *reinterpret_cast<float2*>(&out[(size_t)r * DD + col]) = v;
            }
        }
    }
}

__global__ __launch_bounds__(256) void final_gemm_01(const float* __restrict__ W1, const float* __restrict__ b1,
                                                     const float* __restrict__ W2, const float* __restrict__ b2,
                                                     float* __restrict__ out, int M) {
    final_gemm_body<0, 2, false>(W1, b1, W2, b2, nullptr, nullptr, out, M);
}

__global__ __launch_bounds__(256) void final_gemm_2(const float* __restrict__ W3, const float* __restrict__ b3,
                                                    float* __restrict__ out, int M) {
    final_gemm_body<2, 1, true>(nullptr, nullptr, nullptr, nullptr, W3, b3, out, M);
}

// ---------------------------------------------------------------------------
// Launcher — deep fork/join pipeline:
//   s2:   CSR chain .......... (wait uv) mean_gather ......................
//   main: uv_gemm ... (wait CSR) attn_gather .. gemm01 .. (wait mean) gemm2
// mean_gather depends only on nodeh (uv by==0) + mean CSR, so it overlaps
// the whole attn phase AND gemm01 on the main stream.
// ---------------------------------------------------------------------------
extern "C" void kernel_launch(void* const* d_in, const int* in_sizes, int n_in,
                              void* d_out, int out_size) {
    const float* node   = (const float*)d_in[0];
    const int*   er_src = (const int*)d_in[1];
    const int*   er_dst = (const int*)d_in[2];
    const int*   ee_src = (const int*)d_in[3];
    const int*   ee_dst = (const int*)d_in[4];
    const float* ee_w   = (const float*)d_in[5];
    const int*   rr_src = (const int*)d_in[6];
    const int*   rr_dst = (const int*)d_in[7];
    const float* W_attn = (const float*)d_in[8];
    const float* b_attn = (const float*)d_in[9];
    const float* w0_w   = (const float*)d_in[10];
    const float* w0_b   = (const float*)d_in[11];
    const float* W1     = (const float*)d_in[12];
    const float* b1     = (const float*)d_in[13];
    const float* W2     = (const float*)d_in[14];
    const float* b2     = (const float*)d_in[15];
    const float* W3     = (const float*)d_in[16];
    const float* b3     = (const float*)d_in[17];
    float* out = (float*)d_out;

    int N    = in_sizes[0] / DD;
    int E_er = in_sizes[1];
    int E_ee = in_sizes[3];
    int E_rr = in_sizes[6];

    int Etot    = E_er + E_ee + E_rr;
    int totMean = E_er + E_ee + E_rr;      // mean entries (rebased)
    int n2      = 2 * N;
    int nScanBlk = (n2 + SCAN_BS - 1) / SCAN_BS;

    cudaStream_t s2 = g_res.s2;

    cudaEventRecord(g_res.evFork, 0);
    cudaStreamWaitEvent(s2, g_res.evFork, 0);

    // --- s2: CSR build chain ---
    zero_cnt<<<(n2 + 255) / 256, 256, 0, s2>>>(n2);
    count_edges<<<(Etot + 255) / 256, 256, 0, s2>>>(er_src, er_dst, ee_src, rr_src,
                                                    E_er, E_ee, E_rr);
    scan_a<<<nScanBlk, SCAN_BS, 0, s2>>>(n2);
    scan_b<<<1, SCAN_BS, 0, s2>>>(nScanBlk);
    scan_c<<<nScanBlk, SCAN_BS, 0, s2>>>(n2);
    fill_edges<<<(Etot + 255) / 256, 256, 0, s2>>>(er_src, er_dst, ee_src, ee_dst, ee_w,
                                                   rr_src, rr_dst, E_er, E_ee, E_rr);
    cudaEventRecord(g_res.evCsrDone, s2);

    // --- main stream: u, v projections (also writes fp16 node copy) ---
    {
        dim3 grid((N + 127) / 128, 2);
        uv_gemm_mma<<<grid, 256>>>(node, W_attn, b_attn, N);
    }
    cudaEventRecord(g_res.evUvDone, 0);

    // s2: mean gather (needs nodeh from uv + mean CSR); overlaps attn + gemm01
    cudaStreamWaitEvent(s2, g_res.evUvDone, 0);
    mean_gather<<<(N + 7) / 8, 256, 0, s2>>>(N, E_er, totMean);
    cudaEventRecord(g_res.evMeanDone, s2);

    // main: attn gather (needs uvh + attn CSR)
    cudaStreamWaitEvent(0, g_res.evCsrDone, 0);
    attn_gather<<<(N + 7) / 8, 256>>>(w0_w, w0_b, N, E_er);

    // main: phases 0-1 of the output GEMM (needs nodeh + aggh only)
    final_gemm_01<<<(N + 63) / 64, 256>>>(W1, b1, W2, b2, out, N);

    // join mean gather -> main, then phase 2 accumulate
    cudaStreamWaitEvent(0, g_res.evMeanDone, 0);
    final_gemm_2<<<(N + 63) / 64, 256>>>(W3, b3, out, N);
}